// round 11
// baseline (speedup 1.0000x reference)
#include <cuda_runtime.h>
#include <cuda_fp16.h>
#include <cstdint>
#include <math.h>

// ---------------- problem constants (fixed by reference) ----------------
#define NG   100
#define NPG  500
#define EPG  4000
#define NN   (NG*NPG)      // 50000 nodes
#define NE   (NG*EPG)      // 400000 edges
#define HID  128
#define H4   512
#define PQW  1024          // P (512) || Q (512)
#define KSEL 2000          // ceil(0.5 * 4000)
#define MT_TOT 3125        // NN/16 m16-tiles

// output layout (float32, concatenated in reference return order)
#define O_ATT 0
#define O_CW  (NE)
#define O_SW  (2*NE)
#define O_CM  (3*NE)
#define O_EI  (4*NE)           // [2,E]: new_row then new_col
#define O_NM  (6*NE)
#define O_CX  (6*NE + NN)

// ---------------- scratch (__device__ globals; no allocation) ----------------
// A fragments (fp16x2-packed): [mt 3125][ks16 8][lane 32] -> uint4 {a0,a1,a2,a3}
__device__ uint4         g_ehi[(size_t)MT_TOT * 8 * 32];
__device__ uint4         g_elo[(size_t)MT_TOT * 8 * 32];
// B fragments: [half 2][nt 64][ks16 8][lane 32] -> uint2 {b0,b1}
__device__ uint2         g_wthi[2 * 64 * 8 * 32];
__device__ uint2         g_wtlo[2 * 64 * 8 * 32];
__device__ float         g_PQ[(size_t)NN * PQW];    // ~205 MB
__device__ unsigned char g_cmask[NE];
__device__ int           g_nm[NN];
__device__ int           g_scan[NN];
__device__ int           g_newid[NN];
__device__ int           g_bsum[128];

// ---------------- helpers ----------------
__device__ __forceinline__ unsigned int h2u(__half2 h) { return *(unsigned int*)&h; }

__device__ __forceinline__ void split_f2(float2 v, unsigned int& hi, unsigned int& lo) {
    __half2 h = __float22half2_rn(v);
    float2 hf = __half22float2(h);
    __half2 l = __float22half2_rn(make_float2(v.x - hf.x, v.y - hf.y));
    hi = h2u(h); lo = h2u(l);
}

__device__ __forceinline__ unsigned int f2k(float f) {
    unsigned int u = __float_as_uint(f);
    return (u & 0x80000000u) ? ~u : (u | 0x80000000u);
}
__device__ __forceinline__ float k2f(unsigned int k) {
    unsigned int u = (k & 0x80000000u) ? (k & 0x7FFFFFFFu) : ~k;
    return __uint_as_float(u);
}

// ---------------- warp-level fp16 MMA m16n8k16 (baseline PTX) ----------------
__device__ __forceinline__ void mma_f16(float* d, uint4 a, uint2 b) {
    asm volatile(
        "mma.sync.aligned.m16n8k16.row.col.f32.f16.f16.f32 "
        "{%0,%1,%2,%3}, {%4,%5,%6,%7}, {%8,%9}, {%0,%1,%2,%3};"
        : "+f"(d[0]), "+f"(d[1]), "+f"(d[2]), "+f"(d[3])
        : "r"(a.x), "r"(a.y), "r"(a.z), "r"(a.w), "r"(b.x), "r"(b.y));
}

// ---------------- K0: zero node-mask ----------------
__global__ void k_zero_nm() {
    int n = blockIdx.x * blockDim.x + threadIdx.x;
    if (n < NN) g_nm[n] = 0;
}

// ---------------- K-split: emb -> fp16 hi/lo fragments ----------------
__global__ __launch_bounds__(256) void k_split_emb(const float* __restrict__ emb) {
    int wid  = threadIdx.x >> 5;
    int lane = threadIdx.x & 31;
    int g = lane >> 2, t = lane & 3;
    int task = blockIdx.x * 8 + wid;        // 0 .. 25000-1 exact
    int mt = task >> 3;
    int ks = task & 7;
    int r0 = mt * 16 + g;
    int c0 = ks * 16 + 2 * t;
    float2 v00 = *(const float2*)(emb + (size_t)r0 * HID + c0);
    float2 v10 = *(const float2*)(emb + (size_t)(r0 + 8) * HID + c0);
    float2 v02 = *(const float2*)(emb + (size_t)r0 * HID + c0 + 8);
    float2 v12 = *(const float2*)(emb + (size_t)(r0 + 8) * HID + c0 + 8);
    uint4 h, l;
    split_f2(v00, h.x, l.x);
    split_f2(v10, h.y, l.y);
    split_f2(v02, h.z, l.z);
    split_f2(v12, h.w, l.w);
    size_t idx = (size_t)task * 32 + lane;
    g_ehi[idx] = h;
    g_elo[idx] = l;
}

// ---------------- K-split: W1 -> fp16 hi/lo fragments ----------------
__global__ __launch_bounds__(256) void k_split_w(const float* __restrict__ W1) {
    int wid  = threadIdx.x >> 5;
    int lane = threadIdx.x & 31;
    int g = lane >> 2, t = lane & 3;
    int task = blockIdx.x * 8 + wid;        // 0 .. 1023 exact
    int half = task >> 9;
    int nt   = (task >> 3) & 63;
    int ks   = task & 7;
    int n  = nt * 8 + g;
    int k0 = half * 128 + ks * 16 + 2 * t;
    float2 v0 = make_float2(W1[(size_t)k0 * H4 + n], W1[(size_t)(k0 + 1) * H4 + n]);
    float2 v1 = make_float2(W1[(size_t)(k0 + 8) * H4 + n], W1[(size_t)(k0 + 9) * H4 + n]);
    uint2 h, l;
    split_f2(v0, h.x, l.x);
    split_f2(v1, h.y, l.y);
    size_t idx = (size_t)task * 32 + lane;
    g_wthi[idx] = h;
    g_wtlo[idx] = l;
}

// ---------------- K1: 3xFP16 GEMM, warp tile 64x32 (4x4), 128-thr CTA ----------------
// grid (16, 391): x = 64-wide n-tile of PQ, y = 128-row m-tile (8 m16-tiles).
// CTA 128m x 64n, 4 warps (warpM 2 x warpN 2), warp = 64m x 32n.
// smem 96KB -> 2 CTAs/SM. Per k16-step per warp: 8 LDS.128 + 8 LDS.64 for 48 MMAs.
#define SB_HI 0          // float offsets
#define SB_LO 4096       // B: 8nt*8ks*32 uint2 = 16KB each
#define SA_HI 8192       // A: 8mt*8ks*32 uint4 = 32KB each
#define SA_LO 16384
#define GEMM_DYN (24576*4)   // 98304 bytes

extern __shared__ float gsm[];

__global__ __launch_bounds__(128, 2) void k_gemm_mma(const float* __restrict__ b1) {
    int tid   = threadIdx.x;
    int wid   = tid >> 5;
    int lane  = tid & 31;
    int gquad = lane >> 2;
    int tg    = lane & 3;
    int nbase = blockIdx.x * 64;
    int mbase16 = blockIdx.y * 8;

    int warpM = wid & 1;                   // 2 x 64 rows
    int warpN = wid >> 1;                  // 2 x 32 cols

    int half = nbase >> 9;                 // 0 = P, 1 = Q
    int ntb  = (nbase & 511) >> 3;         // first n8-tile within half (8 per CTA)

    // ---- stage B (8 nt x 8 ks, hi+lo): contiguous copy ----
    {
        size_t src4 = ((size_t)(half * 64 + ntb) * 256) >> 1;   // float4 index into g_wthi
        const float4* sh = (const float4*)g_wthi + src4;
        const float4* sl = (const float4*)g_wtlo + src4;
        #pragma unroll
        for (int l = 0; l < 8; l++) {
            int t = tid + l * 128;                              // 0..1023 float4
            ((float4*)(gsm + SB_HI))[t] = sh[t];
            ((float4*)(gsm + SB_LO))[t] = sl[t];
        }
    }
    // ---- stage A (8 mt x 8 ks, hi+lo): contiguous copy with mt guard ----
    {
        const float4* sh = (const float4*)g_ehi + (size_t)mbase16 * 256;
        const float4* sl = (const float4*)g_elo + (size_t)mbase16 * 256;
        #pragma unroll
        for (int l = 0; l < 16; l++) {
            int t  = tid + l * 128;                             // 0..2047 float4
            int mt = t >> 8;
            float4 vh = make_float4(0.f, 0.f, 0.f, 0.f), vl = vh;
            if (mbase16 + mt < MT_TOT) { vh = sh[t]; vl = sl[t]; }
            ((float4*)(gsm + SA_HI))[t] = vh;
            ((float4*)(gsm + SA_LO))[t] = vl;
        }
    }
    __syncthreads();

    float acc[4][4][4];
    #pragma unroll
    for (int i = 0; i < 4; i++)
        #pragma unroll
        for (int j = 0; j < 4; j++)
            #pragma unroll
            for (int r = 0; r < 4; r++) acc[i][j][r] = 0.f;

    #pragma unroll
    for (int ks = 0; ks < 8; ks++) {
        uint4 ah[4], al[4];
        #pragma unroll
        for (int i = 0; i < 4; i++) {
            int idx = ((warpM * 4 + i) * 8 + ks) * 32 + lane;
            ah[i] = ((const uint4*)(gsm + SA_HI))[idx];
            al[i] = ((const uint4*)(gsm + SA_LO))[idx];
        }
        uint2 bh[4], bl[4];
        #pragma unroll
        for (int j = 0; j < 4; j++) {
            int idx = ((warpN * 4 + j) * 8 + ks) * 32 + lane;
            bh[j] = ((const uint2*)(gsm + SB_HI))[idx];
            bl[j] = ((const uint2*)(gsm + SB_LO))[idx];
        }
        // pass 1: ah * bh (16 independent MMAs)
        #pragma unroll
        for (int j = 0; j < 4; j++)
            #pragma unroll
            for (int i = 0; i < 4; i++) mma_f16(acc[i][j], ah[i], bh[j]);
        // pass 2: ah * bl
        #pragma unroll
        for (int j = 0; j < 4; j++)
            #pragma unroll
            for (int i = 0; i < 4; i++) mma_f16(acc[i][j], ah[i], bl[j]);
        // pass 3: al * bh
        #pragma unroll
        for (int j = 0; j < 4; j++)
            #pragma unroll
            for (int i = 0; i < 4; i++) mma_f16(acc[i][j], al[i], bh[j]);
    }

    // ---- epilogue: add b1 (P half), store float2 pairs ----
    int mbase = mbase16 * 16;
    #pragma unroll
    for (int j = 0; j < 4; j++) {
        int col = nbase + (warpN * 4 + j) * 8 + 2 * tg;   // even
        float2 bv = make_float2(0.f, 0.f);
        if (col < H4) bv = *(const float2*)(b1 + col);
        #pragma unroll
        for (int i = 0; i < 4; i++) {
            int row0 = mbase + warpM * 64 + i * 16 + gquad;
            float* d = acc[i][j];
            if (row0 < NN)
                *(float2*)(g_PQ + (size_t)row0 * PQW + col) =
                    make_float2(d[0] + bv.x, d[1] + bv.y);
            if (row0 + 8 < NN)
                *(float2*)(g_PQ + (size_t)(row0 + 8) * PQW + col) =
                    make_float2(d[2] + bv.x, d[3] + bv.y);
        }
    }
}

// ---------------- K2: edge attention, per-graph smem chunking ----------------
// One CTA per graph, 512 thr. Chunk 32 dims x 16 chunks. Lane = edge, rotated dim
// access (pos=(lane+d)&15 float2 positions) -> conflict-free; no cross-lane reduce.
#define EA_PC   0                  // Pc: 500*32 floats
#define EA_QC   16000              // Qc: 500*32 floats
#define EA_W2   32000              // 32 floats
#define EA_EP   32032              // packed edges: 4096 uints
#define EA_SMEM ((32032 + 4096) * 4)   // 144512 bytes

__global__ __launch_bounds__(512) void k_edge_att(const int* __restrict__ ei,
                                                  const float* __restrict__ W2,
                                                  const float* __restrict__ b2,
                                                  float* __restrict__ out) {
    int g    = blockIdx.x;
    int base = g * EPG;
    int g0   = g * NPG;
    int tid  = threadIdx.x;
    int wid  = tid >> 5;
    int lane = tid & 31;

    // pack local edge endpoints (slots 4000..4095 -> 0)
    for (int i = tid; i < 4096; i += 512) {
        unsigned int pk = 0u;
        if (i < EPG) {
            unsigned int r = (unsigned int)(ei[base + i] - g0);
            unsigned int c = (unsigned int)(ei[NE + base + i] - g0);
            pk = r | (c << 16);
        }
        ((unsigned int*)(gsm + EA_EP))[i] = pk;
    }
    __syncthreads();

    // per-lane groups: slot = (wid*8+gq)*32 + lane
    int pb[8], qb[8];
    #pragma unroll
    for (int gq = 0; gq < 8; gq++) {
        int slot = (wid * 8 + gq) * 32 + lane;
        unsigned int pk = ((const unsigned int*)(gsm + EA_EP))[slot];
        pb[gq] = (int)(pk & 0xFFFFu) * 16;      // float2 index (row stride 16 float2)
        qb[gq] = (int)(pk >> 16) * 16;
    }
    float score[8];
    #pragma unroll
    for (int gq = 0; gq < 8; gq++) score[gq] = 0.f;

    for (int ch = 0; ch < 16; ch++) {
        __syncthreads();
        // stage P/Q chunk: 500 nodes x 8 float4 each
        for (int i = tid; i < 4000; i += 512) {
            int node = i >> 3, q = i & 7;
            const float* rowp = g_PQ + (size_t)(g0 + node) * PQW + ch * 32;
            ((float4*)(gsm + EA_PC))[node * 8 + q] = ((const float4*)rowp)[q];
            ((float4*)(gsm + EA_QC))[node * 8 + q] = ((const float4*)(rowp + H4))[q];
        }
        if (tid < 32) gsm[EA_W2 + tid] = W2[ch * 32 + tid];
        __syncthreads();

        const float2* P2 = (const float2*)(gsm + EA_PC);
        const float2* Q2 = (const float2*)(gsm + EA_QC);
        const float2* W2s = (const float2*)(gsm + EA_W2);
        #pragma unroll
        for (int gq = 0; gq < 8; gq++) {
            int pos = lane & 15;
            float s = 0.f;
            #pragma unroll
            for (int d2 = 0; d2 < 16; d2++) {
                float2 p = P2[pb[gq] + pos];
                float2 q = Q2[qb[gq] + pos];
                float2 w = W2s[pos];
                s += w.x * fmaxf(p.x + q.x, 0.f);
                s += w.y * fmaxf(p.y + q.y, 0.f);
                pos = (pos + 1) & 15;
            }
            score[gq] += s;
        }
    }

    float b2v = b2[0];
    #pragma unroll
    for (int gq = 0; gq < 8; gq++) {
        int slot = (wid * 8 + gq) * 32 + lane;
        if (slot < EPG) out[O_ATT + base + slot] = score[gq] + b2v;
    }
}

// ---------------- K3: per-graph top-k radix select (512 thr, shuffle scans) ----------------
__global__ __launch_bounds__(512) void k_select(const int* __restrict__ ei,
                                                float* __restrict__ out) {
    __shared__ unsigned int skey[EPG];     // 16KB
    __shared__ int hist[256];
    __shared__ int wtmp[16];
    __shared__ unsigned int s_prefix;
    __shared__ int s_kleft;

    int g    = blockIdx.x;
    int tid  = threadIdx.x;
    int lane = tid & 31;
    int wid  = tid >> 5;
    int base = g * EPG;

    for (int i = tid; i < EPG; i += 512) skey[i] = f2k(out[O_ATT + base + i]);
    __syncthreads();

    unsigned int prefix = 0u;
    int kleft = KSEL;
    #pragma unroll
    for (int pass = 3; pass >= 0; pass--) {
        int shift = pass * 8;
        if (tid < 256) hist[tid] = 0;
        __syncthreads();
        unsigned int maskHigh = (pass == 3) ? 0u : (0xFFFFFFFFu << (shift + 8));
        for (int i = tid; i < EPG; i += 512) {
            unsigned int k = skey[i];
            if ((k & maskHigh) == prefix)
                atomicAdd(&hist[(k >> shift) & 255], 1);
        }
        __syncthreads();
        int myh = 0, sfx = 0;
        if (tid < 256) {
            myh = hist[tid];
            sfx = myh;
            #pragma unroll
            for (int off = 1; off < 32; off <<= 1) {
                int t = __shfl_down_sync(0xFFFFFFFFu, sfx, off);
                if (lane + off < 32) sfx += t;
            }
            if (lane == 0) wtmp[wid] = sfx;
        }
        __syncthreads();
        if (tid < 32) {
            int v = (tid < 8) ? wtmp[tid] : 0;
            #pragma unroll
            for (int off = 1; off < 8; off <<= 1) {
                int t = __shfl_down_sync(0xFFFFFFFFu, v, off);
                if (tid + off < 8) v += t;
            }
            if (tid < 8) wtmp[8 + tid] = v;
        }
        __syncthreads();
        if (tid < 256) {
            int incl  = sfx + ((wid < 7) ? wtmp[8 + wid + 1] : 0);
            int above = incl - myh;
            if (above < kleft && incl >= kleft) {
                s_prefix = prefix | ((unsigned int)tid << shift);
                s_kleft  = kleft - above;
            }
        }
        __syncthreads();
        prefix = s_prefix;
        kleft  = s_kleft;
    }
    __syncthreads();
    unsigned int T = prefix;
    int need = kleft;

    // ordered prefix over equality flags; 512*8=4096 > EPG=4000 -> guard everything
    int start = tid * 8;
    int localEq = 0;
    #pragma unroll
    for (int i = 0; i < 8; i++) {
        int idx = start + i;
        if (idx < EPG) localEq += (skey[idx] == T);
    }
    int p = localEq;
    #pragma unroll
    for (int off = 1; off < 32; off <<= 1) {
        int t = __shfl_up_sync(0xFFFFFFFFu, p, off);
        if (lane >= off) p += t;
    }
    if (lane == 31) wtmp[wid] = p;
    __syncthreads();
    if (tid < 32) {
        int v = (tid < 16) ? wtmp[tid] : 0;
        #pragma unroll
        for (int off = 1; off < 16; off <<= 1) {
            int t = __shfl_up_sync(0xFFFFFFFFu, v, off);
            if (tid >= off) v += t;
        }
        if (tid < 16) wtmp[tid] = v;
    }
    __syncthreads();
    int run = (p - localEq) + ((wid > 0) ? wtmp[wid - 1] : 0);

    for (int i = start; i < start + 8 && i < EPG; i++) {
        unsigned int k = skey[i];
        bool causal;
        if (k > T)       causal = true;
        else if (k == T) { causal = (run < need); run++; }
        else             causal = false;
        float att = k2f(k);
        int e = base + i;
        out[O_CW + e] = causal ? att : 0.f;
        out[O_SW + e] = causal ? 0.f : att;
        out[O_CM + e] = causal ? 1.f : 0.f;
        g_cmask[e] = causal ? 1 : 0;
        if (causal) {
            g_nm[ei[e]]      = 1;
            g_nm[ei[NE + e]] = 1;
        }
    }
}

// ---------------- K4/K5: two-level scan of node mask ----------------
__global__ __launch_bounds__(512) void k_scan_a() {
    __shared__ int s[512];
    int tid = threadIdx.x;
    int n = blockIdx.x * 512 + tid;
    int x = (n < NN) ? g_nm[n] : 0;
    s[tid] = x;
    __syncthreads();
    for (int off = 1; off < 512; off <<= 1) {
        int v = (tid >= off) ? s[tid - off] : 0;
        __syncthreads();
        s[tid] += v;
        __syncthreads();
    }
    if (n < NN) g_scan[n] = s[tid];
    if (tid == 511) g_bsum[blockIdx.x] = s[511];
}

__global__ void k_scan_b(int nblk) {
    if (threadIdx.x == 0 && blockIdx.x == 0) {
        int running = 0;
        for (int b = 0; b < nblk; b++) {
            int t = g_bsum[b];
            g_bsum[b] = running;
            running += t;
        }
    }
}

// ---------------- K6: fused node finalize (new_id, node_mask) + causal_x copy ----------------
__global__ void k_nodes(const float* __restrict__ emb, float* __restrict__ out) {
    int i = blockIdx.x * blockDim.x + threadIdx.x;
    if (i >= NN * 32) return;
    int node = i >> 5;
    int nmv = g_nm[node];
    float4 v = make_float4(0.f, 0.f, 0.f, 0.f);
    if (nmv) v = ((const float4*)emb)[i];
    ((float4*)(out + O_CX))[i] = v;
    if ((i & 31) == 0) {
        out[O_NM + node] = nmv ? 1.f : 0.f;
        g_newid[node] = g_scan[node] + g_bsum[node >> 9] - 1;
    }
}

// ---------------- K7: relabeled edge index ----------------
__global__ void k_edge_out(const int* __restrict__ ei, float* __restrict__ out) {
    int e = blockIdx.x * blockDim.x + threadIdx.x;
    if (e >= NE) return;
    bool c = g_cmask[e] != 0;
    int r = ei[e], cc = ei[NE + e];
    out[O_EI + e]      = c ? (float)g_newid[r]  : -1.f;
    out[O_EI + NE + e] = c ? (float)g_newid[cc] : -1.f;
}

// ---------------- launch ----------------
extern "C" void kernel_launch(void* const* d_in, const int* in_sizes, int n_in,
                              void* d_out, int out_size) {
    const float* emb = (const float*)d_in[0];
    const int*   ei  = (const int*)d_in[1];
    // d_in[2] = node_batch (implied by layout: graph = e / EPG)
    const float* W1  = (const float*)d_in[3];
    const float* b1  = (const float*)d_in[4];
    const float* W2  = (const float*)d_in[5];
    const float* b2  = (const float*)d_in[6];
    float* out = (float*)d_out;

    k_zero_nm<<<(NN + 255) / 256, 256>>>();
    k_split_emb<<<MT_TOT, 256>>>(emb);        // 3125 blocks x 8 warps = 25000 tasks
    k_split_w<<<128, 256>>>(W1);              // 1024 tasks

    cudaFuncSetAttribute(k_gemm_mma, cudaFuncAttributeMaxDynamicSharedMemorySize, GEMM_DYN);
    dim3 ggrid(PQW / 64, (NN + 127) / 128);   // (16, 391)
    k_gemm_mma<<<ggrid, 128, GEMM_DYN>>>(b1);

    cudaFuncSetAttribute(k_edge_att, cudaFuncAttributeMaxDynamicSharedMemorySize, EA_SMEM);
    k_edge_att<<<NG, 512, EA_SMEM>>>(ei, W2, b2, out);

    k_select<<<NG, 512>>>(ei, out);

    int nblk = (NN + 511) / 512;            // 98
    k_scan_a<<<nblk, 512>>>();
    k_scan_b<<<1, 32>>>(nblk);

    k_nodes<<<(NN * 32 + 255) / 256, 256>>>(emb, out);
    k_edge_out<<<(NE + 255) / 256, 256>>>(ei, out);
}

// round 12
// speedup vs baseline: 1.0088x; 1.0088x over previous
#include <cuda_runtime.h>
#include <cuda_fp16.h>
#include <cstdint>
#include <math.h>

// ---------------- problem constants (fixed by reference) ----------------
#define NG   100
#define NPG  500
#define EPG  4000
#define NN   (NG*NPG)      // 50000 nodes
#define NE   (NG*EPG)      // 400000 edges
#define HID  128
#define H4   512
#define PQW  1024          // P (512) || Q (512)
#define KSEL 2000          // ceil(0.5 * 4000)
#define MT_TOT 3125        // NN/16 m16-tiles

// output layout (float32, concatenated in reference return order)
#define O_ATT 0
#define O_CW  (NE)
#define O_SW  (2*NE)
#define O_CM  (3*NE)
#define O_EI  (4*NE)           // [2,E]: new_row then new_col
#define O_NM  (6*NE)
#define O_CX  (6*NE + NN)

// ---------------- scratch (__device__ globals; no allocation) ----------------
// A fragments (fp16x2-packed): [mt 3125][ks16 8][lane 32] -> uint4 {a0,a1,a2,a3}
__device__ uint4         g_ehi[(size_t)MT_TOT * 8 * 32];
__device__ uint4         g_elo[(size_t)MT_TOT * 8 * 32];
// B fragments: [half 2][nt 64][ks16 8][lane 32] -> uint2 {b0,b1}
__device__ uint2         g_wthi[2 * 64 * 8 * 32];
__device__ uint2         g_wtlo[2 * 64 * 8 * 32];
__device__ float         g_PQ[(size_t)NN * PQW];    // ~205 MB
__device__ unsigned char g_cmask[NE];
__device__ int           g_nm[NN];
__device__ int           g_scan[NN];
__device__ int           g_newid[NN];
__device__ int           g_bsum[128];

// ---------------- helpers ----------------
__device__ __forceinline__ unsigned int h2u(__half2 h) { return *(unsigned int*)&h; }

__device__ __forceinline__ void split_f2(float2 v, unsigned int& hi, unsigned int& lo) {
    __half2 h = __float22half2_rn(v);
    float2 hf = __half22float2(h);
    __half2 l = __float22half2_rn(make_float2(v.x - hf.x, v.y - hf.y));
    hi = h2u(h); lo = h2u(l);
}

__device__ __forceinline__ unsigned int f2k(float f) {
    unsigned int u = __float_as_uint(f);
    return (u & 0x80000000u) ? ~u : (u | 0x80000000u);
}
__device__ __forceinline__ float k2f(unsigned int k) {
    unsigned int u = (k & 0x80000000u) ? (k & 0x7FFFFFFFu) : ~k;
    return __uint_as_float(u);
}

// ---------------- warp-level fp16 MMA m16n8k16 (baseline PTX) ----------------
__device__ __forceinline__ void mma_f16(float* d, uint4 a, uint2 b) {
    asm volatile(
        "mma.sync.aligned.m16n8k16.row.col.f32.f16.f16.f32 "
        "{%0,%1,%2,%3}, {%4,%5,%6,%7}, {%8,%9}, {%0,%1,%2,%3};"
        : "+f"(d[0]), "+f"(d[1]), "+f"(d[2]), "+f"(d[3])
        : "r"(a.x), "r"(a.y), "r"(a.z), "r"(a.w), "r"(b.x), "r"(b.y));
}

// ---------------- K0: zero node-mask ----------------
__global__ void k_zero_nm() {
    int n = blockIdx.x * blockDim.x + threadIdx.x;
    if (n < NN) g_nm[n] = 0;
}

// ---------------- K-split: emb -> fp16 hi/lo fragments ----------------
__global__ __launch_bounds__(256) void k_split_emb(const float* __restrict__ emb) {
    int wid  = threadIdx.x >> 5;
    int lane = threadIdx.x & 31;
    int g = lane >> 2, t = lane & 3;
    int task = blockIdx.x * 8 + wid;        // 0 .. 25000-1 exact
    int mt = task >> 3;
    int ks = task & 7;
    int r0 = mt * 16 + g;
    int c0 = ks * 16 + 2 * t;
    float2 v00 = *(const float2*)(emb + (size_t)r0 * HID + c0);
    float2 v10 = *(const float2*)(emb + (size_t)(r0 + 8) * HID + c0);
    float2 v02 = *(const float2*)(emb + (size_t)r0 * HID + c0 + 8);
    float2 v12 = *(const float2*)(emb + (size_t)(r0 + 8) * HID + c0 + 8);
    uint4 h, l;
    split_f2(v00, h.x, l.x);
    split_f2(v10, h.y, l.y);
    split_f2(v02, h.z, l.z);
    split_f2(v12, h.w, l.w);
    size_t idx = (size_t)task * 32 + lane;
    g_ehi[idx] = h;
    g_elo[idx] = l;
}

// ---------------- K-split: W1 -> fp16 hi/lo fragments ----------------
__global__ __launch_bounds__(256) void k_split_w(const float* __restrict__ W1) {
    int wid  = threadIdx.x >> 5;
    int lane = threadIdx.x & 31;
    int g = lane >> 2, t = lane & 3;
    int task = blockIdx.x * 8 + wid;        // 0 .. 1023 exact
    int half = task >> 9;
    int nt   = (task >> 3) & 63;
    int ks   = task & 7;
    int n  = nt * 8 + g;
    int k0 = half * 128 + ks * 16 + 2 * t;
    float2 v0 = make_float2(W1[(size_t)k0 * H4 + n], W1[(size_t)(k0 + 1) * H4 + n]);
    float2 v1 = make_float2(W1[(size_t)(k0 + 8) * H4 + n], W1[(size_t)(k0 + 9) * H4 + n]);
    uint2 h, l;
    split_f2(v0, h.x, l.x);
    split_f2(v1, h.y, l.y);
    size_t idx = (size_t)task * 32 + lane;
    g_wthi[idx] = h;
    g_wtlo[idx] = l;
}

// ---------------- K1: 3xFP16 GEMM, warp tile 64x32 (4x4), 128-thr CTA ----------------
// grid (16, 391): x = 64-wide n-tile of PQ, y = 128-row m-tile (8 m16-tiles).
// CTA 128m x 64n, 4 warps (warpM 2 x warpN 2), warp = 64m x 32n.
// smem 96KB -> 2 CTAs/SM. Per k16-step per warp: 8 LDS.128 + 8 LDS.64 for 48 MMAs.
#define SB_HI 0          // float offsets
#define SB_LO 4096       // B: 8nt*8ks*32 uint2 = 16KB each
#define SA_HI 8192       // A: 8mt*8ks*32 uint4 = 32KB each
#define SA_LO 16384
#define GEMM_DYN (24576*4)   // 98304 bytes

extern __shared__ float gsm[];

__global__ __launch_bounds__(128, 2) void k_gemm_mma(const float* __restrict__ b1) {
    int tid   = threadIdx.x;
    int wid   = tid >> 5;
    int lane  = tid & 31;
    int gquad = lane >> 2;
    int tg    = lane & 3;
    int nbase = blockIdx.x * 64;
    int mbase16 = blockIdx.y * 8;

    int warpM = wid & 1;                   // 2 x 64 rows
    int warpN = wid >> 1;                  // 2 x 32 cols

    int half = nbase >> 9;                 // 0 = P, 1 = Q
    int ntb  = (nbase & 511) >> 3;         // first n8-tile within half (8 per CTA)

    // ---- stage B (8 nt x 8 ks, hi+lo): contiguous copy ----
    {
        size_t src4 = ((size_t)(half * 64 + ntb) * 256) >> 1;   // float4 index into g_wthi
        const float4* sh = (const float4*)g_wthi + src4;
        const float4* sl = (const float4*)g_wtlo + src4;
        #pragma unroll
        for (int l = 0; l < 8; l++) {
            int t = tid + l * 128;                              // 0..1023 float4
            ((float4*)(gsm + SB_HI))[t] = sh[t];
            ((float4*)(gsm + SB_LO))[t] = sl[t];
        }
    }
    // ---- stage A (8 mt x 8 ks, hi+lo): contiguous copy with mt guard ----
    {
        const float4* sh = (const float4*)g_ehi + (size_t)mbase16 * 256;
        const float4* sl = (const float4*)g_elo + (size_t)mbase16 * 256;
        #pragma unroll
        for (int l = 0; l < 16; l++) {
            int t  = tid + l * 128;                             // 0..2047 float4
            int mt = t >> 8;
            float4 vh = make_float4(0.f, 0.f, 0.f, 0.f), vl = vh;
            if (mbase16 + mt < MT_TOT) { vh = sh[t]; vl = sl[t]; }
            ((float4*)(gsm + SA_HI))[t] = vh;
            ((float4*)(gsm + SA_LO))[t] = vl;
        }
    }
    __syncthreads();

    float acc[4][4][4];
    #pragma unroll
    for (int i = 0; i < 4; i++)
        #pragma unroll
        for (int j = 0; j < 4; j++)
            #pragma unroll
            for (int r = 0; r < 4; r++) acc[i][j][r] = 0.f;

    #pragma unroll
    for (int ks = 0; ks < 8; ks++) {
        uint4 ah[4], al[4];
        #pragma unroll
        for (int i = 0; i < 4; i++) {
            int idx = ((warpM * 4 + i) * 8 + ks) * 32 + lane;
            ah[i] = ((const uint4*)(gsm + SA_HI))[idx];
            al[i] = ((const uint4*)(gsm + SA_LO))[idx];
        }
        uint2 bh[4], bl[4];
        #pragma unroll
        for (int j = 0; j < 4; j++) {
            int idx = ((warpN * 4 + j) * 8 + ks) * 32 + lane;
            bh[j] = ((const uint2*)(gsm + SB_HI))[idx];
            bl[j] = ((const uint2*)(gsm + SB_LO))[idx];
        }
        // pass 1: ah * bh (16 independent MMAs)
        #pragma unroll
        for (int j = 0; j < 4; j++)
            #pragma unroll
            for (int i = 0; i < 4; i++) mma_f16(acc[i][j], ah[i], bh[j]);
        // pass 2: ah * bl
        #pragma unroll
        for (int j = 0; j < 4; j++)
            #pragma unroll
            for (int i = 0; i < 4; i++) mma_f16(acc[i][j], ah[i], bl[j]);
        // pass 3: al * bh
        #pragma unroll
        for (int j = 0; j < 4; j++)
            #pragma unroll
            for (int i = 0; i < 4; i++) mma_f16(acc[i][j], al[i], bh[j]);
    }

    // ---- epilogue: add b1 (P half), store float2 pairs ----
    int mbase = mbase16 * 16;
    #pragma unroll
    for (int j = 0; j < 4; j++) {
        int col = nbase + (warpN * 4 + j) * 8 + 2 * tg;   // even
        float2 bv = make_float2(0.f, 0.f);
        if (col < H4) bv = *(const float2*)(b1 + col);
        #pragma unroll
        for (int i = 0; i < 4; i++) {
            int row0 = mbase + warpM * 64 + i * 16 + gquad;
            float* d = acc[i][j];
            if (row0 < NN)
                *(float2*)(g_PQ + (size_t)row0 * PQW + col) =
                    make_float2(d[0] + bv.x, d[1] + bv.y);
            if (row0 + 8 < NN)
                *(float2*)(g_PQ + (size_t)(row0 + 8) * PQW + col) =
                    make_float2(d[2] + bv.x, d[3] + bv.y);
        }
    }
}

// ---------------- K2: edge attention, per-graph smem chunking ----------------
// One CTA per graph, 512 thr. Chunk 32 dims x 16 chunks. Lane = edge, rotated dim
// access (pos=(lane+d)&15 float2 positions) -> conflict-free; no cross-lane reduce.
#define EA_PC   0                  // Pc: 500*32 floats
#define EA_QC   16000              // Qc: 500*32 floats
#define EA_W2   32000              // 32 floats
#define EA_EP   32032              // packed edges: 4096 uints
#define EA_SMEM ((32032 + 4096) * 4)   // 144512 bytes

__global__ __launch_bounds__(512) void k_edge_att(const int* __restrict__ ei,
                                                  const float* __restrict__ W2,
                                                  const float* __restrict__ b2,
                                                  float* __restrict__ out) {
    int g    = blockIdx.x;
    int base = g * EPG;
    int g0   = g * NPG;
    int tid  = threadIdx.x;
    int wid  = tid >> 5;
    int lane = tid & 31;

    // pack local edge endpoints (slots 4000..4095 -> 0)
    for (int i = tid; i < 4096; i += 512) {
        unsigned int pk = 0u;
        if (i < EPG) {
            unsigned int r = (unsigned int)(ei[base + i] - g0);
            unsigned int c = (unsigned int)(ei[NE + base + i] - g0);
            pk = r | (c << 16);
        }
        ((unsigned int*)(gsm + EA_EP))[i] = pk;
    }
    __syncthreads();

    // per-lane groups: slot = (wid*8+gq)*32 + lane
    int pb[8], qb[8];
    #pragma unroll
    for (int gq = 0; gq < 8; gq++) {
        int slot = (wid * 8 + gq) * 32 + lane;
        unsigned int pk = ((const unsigned int*)(gsm + EA_EP))[slot];
        pb[gq] = (int)(pk & 0xFFFFu) * 16;      // float2 index (row stride 16 float2)
        qb[gq] = (int)(pk >> 16) * 16;
    }
    float score[8];
    #pragma unroll
    for (int gq = 0; gq < 8; gq++) score[gq] = 0.f;

    for (int ch = 0; ch < 16; ch++) {
        __syncthreads();
        // stage P/Q chunk: 500 nodes x 8 float4 each
        for (int i = tid; i < 4000; i += 512) {
            int node = i >> 3, q = i & 7;
            const float* rowp = g_PQ + (size_t)(g0 + node) * PQW + ch * 32;
            ((float4*)(gsm + EA_PC))[node * 8 + q] = ((const float4*)rowp)[q];
            ((float4*)(gsm + EA_QC))[node * 8 + q] = ((const float4*)(rowp + H4))[q];
        }
        if (tid < 32) gsm[EA_W2 + tid] = W2[ch * 32 + tid];
        __syncthreads();

        const float2* P2 = (const float2*)(gsm + EA_PC);
        const float2* Q2 = (const float2*)(gsm + EA_QC);
        const float2* W2s = (const float2*)(gsm + EA_W2);
        #pragma unroll
        for (int gq = 0; gq < 8; gq++) {
            int pos = lane & 15;
            float s = 0.f;
            #pragma unroll
            for (int d2 = 0; d2 < 16; d2++) {
                float2 p = P2[pb[gq] + pos];
                float2 q = Q2[qb[gq] + pos];
                float2 w = W2s[pos];
                s += w.x * fmaxf(p.x + q.x, 0.f);
                s += w.y * fmaxf(p.y + q.y, 0.f);
                pos = (pos + 1) & 15;
            }
            score[gq] += s;
        }
    }

    float b2v = b2[0];
    #pragma unroll
    for (int gq = 0; gq < 8; gq++) {
        int slot = (wid * 8 + gq) * 32 + lane;
        if (slot < EPG) out[O_ATT + base + slot] = score[gq] + b2v;
    }
}

// ---------------- K3: per-graph top-k radix select (512 thr, shuffle scans) ----------------
__global__ __launch_bounds__(512) void k_select(const int* __restrict__ ei,
                                                float* __restrict__ out) {
    __shared__ unsigned int skey[EPG];     // 16KB
    __shared__ int hist[256];
    __shared__ int wtmp[16];
    __shared__ unsigned int s_prefix;
    __shared__ int s_kleft;

    int g    = blockIdx.x;
    int tid  = threadIdx.x;
    int lane = tid & 31;
    int wid  = tid >> 5;
    int base = g * EPG;

    for (int i = tid; i < EPG; i += 512) skey[i] = f2k(out[O_ATT + base + i]);
    __syncthreads();

    unsigned int prefix = 0u;
    int kleft = KSEL;
    #pragma unroll
    for (int pass = 3; pass >= 0; pass--) {
        int shift = pass * 8;
        if (tid < 256) hist[tid] = 0;
        __syncthreads();
        unsigned int maskHigh = (pass == 3) ? 0u : (0xFFFFFFFFu << (shift + 8));
        for (int i = tid; i < EPG; i += 512) {
            unsigned int k = skey[i];
            if ((k & maskHigh) == prefix)
                atomicAdd(&hist[(k >> shift) & 255], 1);
        }
        __syncthreads();
        int myh = 0, sfx = 0;
        if (tid < 256) {
            myh = hist[tid];
            sfx = myh;
            #pragma unroll
            for (int off = 1; off < 32; off <<= 1) {
                int t = __shfl_down_sync(0xFFFFFFFFu, sfx, off);
                if (lane + off < 32) sfx += t;
            }
            if (lane == 0) wtmp[wid] = sfx;
        }
        __syncthreads();
        if (tid < 32) {
            int v = (tid < 8) ? wtmp[tid] : 0;
            #pragma unroll
            for (int off = 1; off < 8; off <<= 1) {
                int t = __shfl_down_sync(0xFFFFFFFFu, v, off);
                if (tid + off < 8) v += t;
            }
            if (tid < 8) wtmp[8 + tid] = v;
        }
        __syncthreads();
        if (tid < 256) {
            int incl  = sfx + ((wid < 7) ? wtmp[8 + wid + 1] : 0);
            int above = incl - myh;
            if (above < kleft && incl >= kleft) {
                s_prefix = prefix | ((unsigned int)tid << shift);
                s_kleft  = kleft - above;
            }
        }
        __syncthreads();
        prefix = s_prefix;
        kleft  = s_kleft;
    }
    __syncthreads();
    unsigned int T = prefix;
    int need = kleft;

    // ordered prefix over equality flags; 512*8=4096 > EPG=4000 -> guard everything
    int start = tid * 8;
    int localEq = 0;
    #pragma unroll
    for (int i = 0; i < 8; i++) {
        int idx = start + i;
        if (idx < EPG) localEq += (skey[idx] == T);
    }
    int p = localEq;
    #pragma unroll
    for (int off = 1; off < 32; off <<= 1) {
        int t = __shfl_up_sync(0xFFFFFFFFu, p, off);
        if (lane >= off) p += t;
    }
    if (lane == 31) wtmp[wid] = p;
    __syncthreads();
    if (tid < 32) {
        int v = (tid < 16) ? wtmp[tid] : 0;
        #pragma unroll
        for (int off = 1; off < 16; off <<= 1) {
            int t = __shfl_up_sync(0xFFFFFFFFu, v, off);
            if (tid >= off) v += t;
        }
        if (tid < 16) wtmp[tid] = v;
    }
    __syncthreads();
    int run = (p - localEq) + ((wid > 0) ? wtmp[wid - 1] : 0);

    for (int i = start; i < start + 8 && i < EPG; i++) {
        unsigned int k = skey[i];
        bool causal;
        if (k > T)       causal = true;
        else if (k == T) { causal = (run < need); run++; }
        else             causal = false;
        float att = k2f(k);
        int e = base + i;
        out[O_CW + e] = causal ? att : 0.f;
        out[O_SW + e] = causal ? 0.f : att;
        out[O_CM + e] = causal ? 1.f : 0.f;
        g_cmask[e] = causal ? 1 : 0;
        if (causal) {
            g_nm[ei[e]]      = 1;
            g_nm[ei[NE + e]] = 1;
        }
    }
}

// ---------------- K4/K5: two-level scan of node mask ----------------
__global__ __launch_bounds__(512) void k_scan_a() {
    __shared__ int s[512];
    int tid = threadIdx.x;
    int n = blockIdx.x * 512 + tid;
    int x = (n < NN) ? g_nm[n] : 0;
    s[tid] = x;
    __syncthreads();
    for (int off = 1; off < 512; off <<= 1) {
        int v = (tid >= off) ? s[tid - off] : 0;
        __syncthreads();
        s[tid] += v;
        __syncthreads();
    }
    if (n < NN) g_scan[n] = s[tid];
    if (tid == 511) g_bsum[blockIdx.x] = s[511];
}

__global__ void k_scan_b(int nblk) {
    if (threadIdx.x == 0 && blockIdx.x == 0) {
        int running = 0;
        for (int b = 0; b < nblk; b++) {
            int t = g_bsum[b];
            g_bsum[b] = running;
            running += t;
        }
    }
}

// ---------------- K6: fused node finalize (new_id, node_mask) + causal_x copy ----------------
__global__ void k_nodes(const float* __restrict__ emb, float* __restrict__ out) {
    int i = blockIdx.x * blockDim.x + threadIdx.x;
    if (i >= NN * 32) return;
    int node = i >> 5;
    int nmv = g_nm[node];
    float4 v = make_float4(0.f, 0.f, 0.f, 0.f);
    if (nmv) v = ((const float4*)emb)[i];
    ((float4*)(out + O_CX))[i] = v;
    if ((i & 31) == 0) {
        out[O_NM + node] = nmv ? 1.f : 0.f;
        g_newid[node] = g_scan[node] + g_bsum[node >> 9] - 1;
    }
}

// ---------------- K7: relabeled edge index ----------------
__global__ void k_edge_out(const int* __restrict__ ei, float* __restrict__ out) {
    int e = blockIdx.x * blockDim.x + threadIdx.x;
    if (e >= NE) return;
    bool c = g_cmask[e] != 0;
    int r = ei[e], cc = ei[NE + e];
    out[O_EI + e]      = c ? (float)g_newid[r]  : -1.f;
    out[O_EI + NE + e] = c ? (float)g_newid[cc] : -1.f;
}

// ---------------- launch ----------------
extern "C" void kernel_launch(void* const* d_in, const int* in_sizes, int n_in,
                              void* d_out, int out_size) {
    const float* emb = (const float*)d_in[0];
    const int*   ei  = (const int*)d_in[1];
    // d_in[2] = node_batch (implied by layout: graph = e / EPG)
    const float* W1  = (const float*)d_in[3];
    const float* b1  = (const float*)d_in[4];
    const float* W2  = (const float*)d_in[5];
    const float* b2  = (const float*)d_in[6];
    float* out = (float*)d_out;

    k_zero_nm<<<(NN + 255) / 256, 256>>>();
    k_split_emb<<<MT_TOT, 256>>>(emb);        // 3125 blocks x 8 warps = 25000 tasks
    k_split_w<<<128, 256>>>(W1);              // 1024 tasks

    cudaFuncSetAttribute(k_gemm_mma, cudaFuncAttributeMaxDynamicSharedMemorySize, GEMM_DYN);
    dim3 ggrid(PQW / 64, (NN + 127) / 128);   // (16, 391)
    k_gemm_mma<<<ggrid, 128, GEMM_DYN>>>(b1);

    cudaFuncSetAttribute(k_edge_att, cudaFuncAttributeMaxDynamicSharedMemorySize, EA_SMEM);
    k_edge_att<<<NG, 512, EA_SMEM>>>(ei, W2, b2, out);

    k_select<<<NG, 512>>>(ei, out);

    int nblk = (NN + 511) / 512;            // 98
    k_scan_a<<<nblk, 512>>>();
    k_scan_b<<<1, 32>>>(nblk);

    k_nodes<<<(NN * 32 + 255) / 256, 256>>>(emb, out);
    k_edge_out<<<(NE + 255) / 256, 256>>>(ei, out);
}

// round 13
// speedup vs baseline: 2.0592x; 2.0413x over previous
#include <cuda_runtime.h>
#include <cuda_fp16.h>
#include <cstdint>
#include <math.h>

// ---------------- problem constants (fixed by reference) ----------------
#define NG   100
#define NPG  500
#define EPG  4000
#define NN   (NG*NPG)      // 50000 nodes
#define NE   (NG*EPG)      // 400000 edges
#define HID  128
#define H4   512
#define PQW  1024          // P (512) || Q (512)
#define KSEL 2000          // ceil(0.5 * 4000)
#define MT_TOT 3125        // NN/16 m16-tiles

// output layout (float32, concatenated in reference return order)
#define O_ATT 0
#define O_CW  (NE)
#define O_SW  (2*NE)
#define O_CM  (3*NE)
#define O_EI  (4*NE)           // [2,E]: new_row then new_col
#define O_NM  (6*NE)
#define O_CX  (6*NE + NN)

// ---------------- scratch (__device__ globals; no allocation) ----------------
// A fragments (fp16x2-packed): [mt 3125][ks16 8][lane 32] -> uint4 {a0,a1,a2,a3}
__device__ uint4         g_ehi[(size_t)MT_TOT * 8 * 32];
__device__ uint4         g_elo[(size_t)MT_TOT * 8 * 32];
// B fragments: [half 2][nt 64][ks16 8][lane 32] -> uint2 {b0,b1}
__device__ uint2         g_wthi[2 * 64 * 8 * 32];
__device__ uint2         g_wtlo[2 * 64 * 8 * 32];
__device__ float         g_PQ[(size_t)NN * PQW];    // ~205 MB
__device__ int           g_eorder[NE];              // edges sorted by src (per graph)
__device__ unsigned char g_cmask[NE];
__device__ int           g_nm[NN];
__device__ int           g_scan[NN];
__device__ int           g_newid[NN];
__device__ int           g_bsum[128];

// ---------------- helpers ----------------
__device__ __forceinline__ unsigned int h2u(__half2 h) { return *(unsigned int*)&h; }

__device__ __forceinline__ void split_f2(float2 v, unsigned int& hi, unsigned int& lo) {
    __half2 h = __float22half2_rn(v);
    float2 hf = __half22float2(h);
    __half2 l = __float22half2_rn(make_float2(v.x - hf.x, v.y - hf.y));
    hi = h2u(h); lo = h2u(l);
}

__device__ __forceinline__ unsigned int f2k(float f) {
    unsigned int u = __float_as_uint(f);
    return (u & 0x80000000u) ? ~u : (u | 0x80000000u);
}
__device__ __forceinline__ float k2f(unsigned int k) {
    unsigned int u = (k & 0x80000000u) ? (k & 0x7FFFFFFFu) : ~k;
    return __uint_as_float(u);
}

// ---------------- warp-level fp16 MMA m16n8k16 (baseline PTX) ----------------
__device__ __forceinline__ void mma_f16(float* d, uint4 a, uint2 b) {
    asm volatile(
        "mma.sync.aligned.m16n8k16.row.col.f32.f16.f16.f32 "
        "{%0,%1,%2,%3}, {%4,%5,%6,%7}, {%8,%9}, {%0,%1,%2,%3};"
        : "+f"(d[0]), "+f"(d[1]), "+f"(d[2]), "+f"(d[3])
        : "r"(a.x), "r"(a.y), "r"(a.z), "r"(a.w), "r"(b.x), "r"(b.y));
}

// ---------------- K0: zero node-mask ----------------
__global__ void k_zero_nm() {
    int n = blockIdx.x * blockDim.x + threadIdx.x;
    if (n < NN) g_nm[n] = 0;
}

// ---------------- K-split: emb -> fp16 hi/lo fragments ----------------
__global__ __launch_bounds__(256) void k_split_emb(const float* __restrict__ emb) {
    int wid  = threadIdx.x >> 5;
    int lane = threadIdx.x & 31;
    int g = lane >> 2, t = lane & 3;
    int task = blockIdx.x * 8 + wid;        // 0 .. 25000-1 exact
    int mt = task >> 3;
    int ks = task & 7;
    int r0 = mt * 16 + g;
    int c0 = ks * 16 + 2 * t;
    float2 v00 = *(const float2*)(emb + (size_t)r0 * HID + c0);
    float2 v10 = *(const float2*)(emb + (size_t)(r0 + 8) * HID + c0);
    float2 v02 = *(const float2*)(emb + (size_t)r0 * HID + c0 + 8);
    float2 v12 = *(const float2*)(emb + (size_t)(r0 + 8) * HID + c0 + 8);
    uint4 h, l;
    split_f2(v00, h.x, l.x);
    split_f2(v10, h.y, l.y);
    split_f2(v02, h.z, l.z);
    split_f2(v12, h.w, l.w);
    size_t idx = (size_t)task * 32 + lane;
    g_ehi[idx] = h;
    g_elo[idx] = l;
}

// ---------------- K-split: W1 -> fp16 hi/lo fragments ----------------
__global__ __launch_bounds__(256) void k_split_w(const float* __restrict__ W1) {
    int wid  = threadIdx.x >> 5;
    int lane = threadIdx.x & 31;
    int g = lane >> 2, t = lane & 3;
    int task = blockIdx.x * 8 + wid;        // 0 .. 1023 exact
    int half = task >> 9;
    int nt   = (task >> 3) & 63;
    int ks   = task & 7;
    int n  = nt * 8 + g;
    int k0 = half * 128 + ks * 16 + 2 * t;
    float2 v0 = make_float2(W1[(size_t)k0 * H4 + n], W1[(size_t)(k0 + 1) * H4 + n]);
    float2 v1 = make_float2(W1[(size_t)(k0 + 8) * H4 + n], W1[(size_t)(k0 + 9) * H4 + n]);
    uint2 h, l;
    split_f2(v0, h.x, l.x);
    split_f2(v1, h.y, l.y);
    size_t idx = (size_t)task * 32 + lane;
    g_wthi[idx] = h;
    g_wtlo[idx] = l;
}

// ---------------- K-sort: per-graph counting sort of edges by src ----------------
__global__ __launch_bounds__(512) void k_sort(const int* __restrict__ ei) {
    __shared__ int hist[512];
    __shared__ int wtmp[16];
    int g    = blockIdx.x;
    int tid  = threadIdx.x;
    int lane = tid & 31;
    int wid  = tid >> 5;
    int base = g * EPG;
    int g0   = g * NPG;

    hist[tid] = 0;
    __syncthreads();
    for (int i = tid; i < EPG; i += 512)
        atomicAdd(&hist[ei[base + i] - g0], 1);
    __syncthreads();

    // exclusive prefix over 512 bins (shuffle scan)
    int v = hist[tid];
    int p = v;
    #pragma unroll
    for (int off = 1; off < 32; off <<= 1) {
        int t = __shfl_up_sync(0xFFFFFFFFu, p, off);
        if (lane >= off) p += t;
    }
    if (lane == 31) wtmp[wid] = p;
    __syncthreads();
    if (tid < 32) {
        int w = (tid < 16) ? wtmp[tid] : 0;
        #pragma unroll
        for (int off = 1; off < 16; off <<= 1) {
            int t = __shfl_up_sync(0xFFFFFFFFu, w, off);
            if (tid >= off) w += t;
        }
        if (tid < 16) wtmp[tid] = w;
    }
    __syncthreads();
    int excl = p - v + ((wid > 0) ? wtmp[wid - 1] : 0);
    __syncthreads();
    hist[tid] = excl;
    __syncthreads();

    for (int i = tid; i < EPG; i += 512) {
        int s   = ei[base + i] - g0;
        int pos = atomicAdd(&hist[s], 1);
        g_eorder[base + pos] = base + i;     // global edge id, sorted by src
    }
}

// ---------------- K1: 3xFP16 GEMM via mma.sync m16n8k16 (R10 config) ----------------
// grid (16, 391): x = 64-wide n-tile of PQ, y = 128-row m-tile (8 m16-tiles).
// CTA 128m x 64n, 8 warps (warpM 2 x warpN 4), warp = 64m x 16n. smem 96KB -> 2 CTAs/SM.
#define SB_HI 0          // float offsets
#define SB_LO 4096       // B: 8nt*8ks*32 uint2 = 16KB each
#define SA_HI 8192       // A: 8mt*8ks*32 uint4 = 32KB each
#define SA_LO 16384
#define GEMM_DYN (24576*4)   // 98304 bytes

extern __shared__ float gsm[];

__global__ __launch_bounds__(256, 2) void k_gemm_mma(const float* __restrict__ b1) {
    int tid   = threadIdx.x;
    int wid   = tid >> 5;
    int lane  = tid & 31;
    int gquad = lane >> 2;
    int tg    = lane & 3;
    int nbase = blockIdx.x * 64;
    int mbase16 = blockIdx.y * 8;

    int warpM = wid & 1;                   // 2 x 64 rows
    int warpN = wid >> 1;                  // 4 x 16 cols

    int half = nbase >> 9;                 // 0 = P, 1 = Q
    int ntb  = (nbase & 511) >> 3;         // first n8-tile within half (8 per CTA)

    // ---- stage B (8 nt x 8 ks, hi+lo): contiguous copy ----
    {
        size_t src4 = ((size_t)(half * 64 + ntb) * 256) >> 1;   // float4 index into g_wthi
        const float4* sh = (const float4*)g_wthi + src4;
        const float4* sl = (const float4*)g_wtlo + src4;
        #pragma unroll
        for (int l = 0; l < 4; l++) {
            int t = tid + l * 256;                              // 0..1023 float4
            ((float4*)(gsm + SB_HI))[t] = sh[t];
            ((float4*)(gsm + SB_LO))[t] = sl[t];
        }
    }
    // ---- stage A (8 mt x 8 ks, hi+lo): contiguous copy with mt guard ----
    {
        const float4* sh = (const float4*)g_ehi + (size_t)mbase16 * 256;
        const float4* sl = (const float4*)g_elo + (size_t)mbase16 * 256;
        #pragma unroll
        for (int l = 0; l < 8; l++) {
            int t  = tid + l * 256;                             // 0..2047 float4
            int mt = t >> 8;
            float4 vh = make_float4(0.f, 0.f, 0.f, 0.f), vl = vh;
            if (mbase16 + mt < MT_TOT) { vh = sh[t]; vl = sl[t]; }
            ((float4*)(gsm + SA_HI))[t] = vh;
            ((float4*)(gsm + SA_LO))[t] = vl;
        }
    }
    __syncthreads();

    float acc[4][2][4];
    #pragma unroll
    for (int i = 0; i < 4; i++)
        #pragma unroll
        for (int j = 0; j < 2; j++)
            #pragma unroll
            for (int r = 0; r < 4; r++) acc[i][j][r] = 0.f;

    #pragma unroll
    for (int ks = 0; ks < 8; ks++) {
        uint4 ah[4], al[4];
        #pragma unroll
        for (int i = 0; i < 4; i++) {
            int idx = ((warpM * 4 + i) * 8 + ks) * 32 + lane;
            ah[i] = ((const uint4*)(gsm + SA_HI))[idx];
            al[i] = ((const uint4*)(gsm + SA_LO))[idx];
        }
        uint2 bh[2], bl[2];
        #pragma unroll
        for (int j = 0; j < 2; j++) {
            int idx = ((warpN * 2 + j) * 8 + ks) * 32 + lane;
            bh[j] = ((const uint2*)(gsm + SB_HI))[idx];
            bl[j] = ((const uint2*)(gsm + SB_LO))[idx];
        }
        // pass 1: ah * bh (8 independent MMAs)
        #pragma unroll
        for (int j = 0; j < 2; j++)
            #pragma unroll
            for (int i = 0; i < 4; i++) mma_f16(acc[i][j], ah[i], bh[j]);
        // pass 2: ah * bl
        #pragma unroll
        for (int j = 0; j < 2; j++)
            #pragma unroll
            for (int i = 0; i < 4; i++) mma_f16(acc[i][j], ah[i], bl[j]);
        // pass 3: al * bh
        #pragma unroll
        for (int j = 0; j < 2; j++)
            #pragma unroll
            for (int i = 0; i < 4; i++) mma_f16(acc[i][j], al[i], bh[j]);
    }

    // ---- epilogue: add b1 (P half), store float2 pairs ----
    int mbase = mbase16 * 16;
    #pragma unroll
    for (int j = 0; j < 2; j++) {
        int col = nbase + warpN * 16 + j * 8 + 2 * tg;   // even
        float2 bv = make_float2(0.f, 0.f);
        if (col < H4) bv = *(const float2*)(b1 + col);
        #pragma unroll
        for (int i = 0; i < 4; i++) {
            int row0 = mbase + warpM * 64 + i * 16 + gquad;
            float* d = acc[i][j];
            if (row0 < NN)
                *(float2*)(g_PQ + (size_t)row0 * PQW + col) =
                    make_float2(d[0] + bv.x, d[1] + bv.y);
            if (row0 + 8 < NN)
                *(float2*)(g_PQ + (size_t)(row0 + 8) * PQW + col) =
                    make_float2(d[2] + bv.x, d[3] + bv.y);
        }
    }
}

// ---------------- K2: edge attention, one warp per SORTED edge ----------------
// Warps walk edges in src-sorted order -> the 8 warps of a CTA share ~1 src row,
// so the P gather hits L1 after the first fetch. Output written to original slot.
__global__ __launch_bounds__(256) void k_edge_att(const int* __restrict__ ei,
                                                  const float* __restrict__ W2,
                                                  const float* __restrict__ b2,
                                                  float* __restrict__ out) {
    __shared__ __align__(16) float sw2[H4];
    int tid = threadIdx.x;
    for (int i = tid; i < H4; i += blockDim.x) sw2[i] = W2[i];
    __syncthreads();

    int gw   = (blockIdx.x * blockDim.x + tid) >> 5;
    int lane = tid & 31;
    if (gw >= NE) return;
    int e = g_eorder[gw];
    int r = ei[e];
    int c = ei[NE + e];
    const float4* Pr = (const float4*)(g_PQ + (size_t)r * PQW);
    const float4* Qr = (const float4*)(g_PQ + (size_t)c * PQW + H4);
    const float4* W4 = (const float4*)sw2;

    float acc = 0.f;
    #pragma unroll
    for (int it = 0; it < 4; it++) {
        int j4 = it * 32 + lane;
        float4 p = Pr[j4];
        float4 q = Qr[j4];
        float4 ww = W4[j4];
        acc += ww.x * fmaxf(p.x + q.x, 0.f);
        acc += ww.y * fmaxf(p.y + q.y, 0.f);
        acc += ww.z * fmaxf(p.z + q.z, 0.f);
        acc += ww.w * fmaxf(p.w + q.w, 0.f);
    }
    #pragma unroll
    for (int off = 16; off > 0; off >>= 1)
        acc += __shfl_xor_sync(0xFFFFFFFFu, acc, off);
    if (lane == 0) out[O_ATT + e] = acc + b2[0];
}

// ---------------- K3: per-graph top-k radix select (512 thr, shuffle scans) ----------------
__global__ __launch_bounds__(512) void k_select(const int* __restrict__ ei,
                                                float* __restrict__ out) {
    __shared__ unsigned int skey[EPG];     // 16KB
    __shared__ int hist[256];
    __shared__ int wtmp[16];
    __shared__ unsigned int s_prefix;
    __shared__ int s_kleft;

    int g    = blockIdx.x;
    int tid  = threadIdx.x;
    int lane = tid & 31;
    int wid  = tid >> 5;
    int base = g * EPG;

    for (int i = tid; i < EPG; i += 512) skey[i] = f2k(out[O_ATT + base + i]);
    __syncthreads();

    unsigned int prefix = 0u;
    int kleft = KSEL;
    #pragma unroll
    for (int pass = 3; pass >= 0; pass--) {
        int shift = pass * 8;
        if (tid < 256) hist[tid] = 0;
        __syncthreads();
        unsigned int maskHigh = (pass == 3) ? 0u : (0xFFFFFFFFu << (shift + 8));
        for (int i = tid; i < EPG; i += 512) {
            unsigned int k = skey[i];
            if ((k & maskHigh) == prefix)
                atomicAdd(&hist[(k >> shift) & 255], 1);
        }
        __syncthreads();
        int myh = 0, sfx = 0;
        if (tid < 256) {
            myh = hist[tid];
            sfx = myh;
            #pragma unroll
            for (int off = 1; off < 32; off <<= 1) {
                int t = __shfl_down_sync(0xFFFFFFFFu, sfx, off);
                if (lane + off < 32) sfx += t;
            }
            if (lane == 0) wtmp[wid] = sfx;
        }
        __syncthreads();
        if (tid < 32) {
            int v = (tid < 8) ? wtmp[tid] : 0;
            #pragma unroll
            for (int off = 1; off < 8; off <<= 1) {
                int t = __shfl_down_sync(0xFFFFFFFFu, v, off);
                if (tid + off < 8) v += t;
            }
            if (tid < 8) wtmp[8 + tid] = v;
        }
        __syncthreads();
        if (tid < 256) {
            int incl  = sfx + ((wid < 7) ? wtmp[8 + wid + 1] : 0);
            int above = incl - myh;
            if (above < kleft && incl >= kleft) {
                s_prefix = prefix | ((unsigned int)tid << shift);
                s_kleft  = kleft - above;
            }
        }
        __syncthreads();
        prefix = s_prefix;
        kleft  = s_kleft;
    }
    __syncthreads();
    unsigned int T = prefix;
    int need = kleft;

    // ordered prefix over equality flags; 512*8=4096 > EPG=4000 -> guard everything
    int start = tid * 8;
    int localEq = 0;
    #pragma unroll
    for (int i = 0; i < 8; i++) {
        int idx = start + i;
        if (idx < EPG) localEq += (skey[idx] == T);
    }
    int p = localEq;
    #pragma unroll
    for (int off = 1; off < 32; off <<= 1) {
        int t = __shfl_up_sync(0xFFFFFFFFu, p, off);
        if (lane >= off) p += t;
    }
    if (lane == 31) wtmp[wid] = p;
    __syncthreads();
    if (tid < 32) {
        int v = (tid < 16) ? wtmp[tid] : 0;
        #pragma unroll
        for (int off = 1; off < 16; off <<= 1) {
            int t = __shfl_up_sync(0xFFFFFFFFu, v, off);
            if (tid >= off) v += t;
        }
        if (tid < 16) wtmp[tid] = v;
    }
    __syncthreads();
    int run = (p - localEq) + ((wid > 0) ? wtmp[wid - 1] : 0);

    for (int i = start; i < start + 8 && i < EPG; i++) {
        unsigned int k = skey[i];
        bool causal;
        if (k > T)       causal = true;
        else if (k == T) { causal = (run < need); run++; }
        else             causal = false;
        float att = k2f(k);
        int e = base + i;
        out[O_CW + e] = causal ? att : 0.f;
        out[O_SW + e] = causal ? 0.f : att;
        out[O_CM + e] = causal ? 1.f : 0.f;
        g_cmask[e] = causal ? 1 : 0;
        if (causal) {
            g_nm[ei[e]]      = 1;
            g_nm[ei[NE + e]] = 1;
        }
    }
}

// ---------------- K4/K5: two-level scan of node mask ----------------
__global__ __launch_bounds__(512) void k_scan_a() {
    __shared__ int s[512];
    int tid = threadIdx.x;
    int n = blockIdx.x * 512 + tid;
    int x = (n < NN) ? g_nm[n] : 0;
    s[tid] = x;
    __syncthreads();
    for (int off = 1; off < 512; off <<= 1) {
        int v = (tid >= off) ? s[tid - off] : 0;
        __syncthreads();
        s[tid] += v;
        __syncthreads();
    }
    if (n < NN) g_scan[n] = s[tid];
    if (tid == 511) g_bsum[blockIdx.x] = s[511];
}

__global__ void k_scan_b(int nblk) {
    if (threadIdx.x == 0 && blockIdx.x == 0) {
        int running = 0;
        for (int b = 0; b < nblk; b++) {
            int t = g_bsum[b];
            g_bsum[b] = running;
            running += t;
        }
    }
}

// ---------------- K6: fused node finalize (new_id, node_mask) + causal_x copy ----------------
__global__ void k_nodes(const float* __restrict__ emb, float* __restrict__ out) {
    int i = blockIdx.x * blockDim.x + threadIdx.x;
    if (i >= NN * 32) return;
    int node = i >> 5;
    int nmv = g_nm[node];
    float4 v = make_float4(0.f, 0.f, 0.f, 0.f);
    if (nmv) v = ((const float4*)emb)[i];
    ((float4*)(out + O_CX))[i] = v;
    if ((i & 31) == 0) {
        out[O_NM + node] = nmv ? 1.f : 0.f;
        g_newid[node] = g_scan[node] + g_bsum[node >> 9] - 1;
    }
}

// ---------------- K7: relabeled edge index ----------------
__global__ void k_edge_out(const int* __restrict__ ei, float* __restrict__ out) {
    int e = blockIdx.x * blockDim.x + threadIdx.x;
    if (e >= NE) return;
    bool c = g_cmask[e] != 0;
    int r = ei[e], cc = ei[NE + e];
    out[O_EI + e]      = c ? (float)g_newid[r]  : -1.f;
    out[O_EI + NE + e] = c ? (float)g_newid[cc] : -1.f;
}

// ---------------- launch ----------------
extern "C" void kernel_launch(void* const* d_in, const int* in_sizes, int n_in,
                              void* d_out, int out_size) {
    const float* emb = (const float*)d_in[0];
    const int*   ei  = (const int*)d_in[1];
    // d_in[2] = node_batch (implied by layout: graph = e / EPG)
    const float* W1  = (const float*)d_in[3];
    const float* b1  = (const float*)d_in[4];
    const float* W2  = (const float*)d_in[5];
    const float* b2  = (const float*)d_in[6];
    float* out = (float*)d_out;

    k_zero_nm<<<(NN + 255) / 256, 256>>>();
    k_split_emb<<<MT_TOT, 256>>>(emb);        // 3125 blocks x 8 warps = 25000 tasks
    k_split_w<<<128, 256>>>(W1);              // 1024 tasks
    k_sort<<<NG, 512>>>(ei);                  // src-sorted edge order

    cudaFuncSetAttribute(k_gemm_mma, cudaFuncAttributeMaxDynamicSharedMemorySize, GEMM_DYN);
    dim3 ggrid(PQW / 64, (NN + 127) / 128);   // (16, 391)
    k_gemm_mma<<<ggrid, 256, GEMM_DYN>>>(b1);

    k_edge_att<<<(NE * 32 + 255) / 256, 256>>>(ei, W2, b2, out);

    k_select<<<NG, 512>>>(ei, out);

    int nblk = (NN + 511) / 512;            // 98
    k_scan_a<<<nblk, 512>>>();
    k_scan_b<<<1, 32>>>(nblk);

    k_nodes<<<(NN * 32 + 255) / 256, 256>>>(emb, out);
    k_edge_out<<<(NE + 255) / 256, 256>>>(ei, out);
}

// round 14
// speedup vs baseline: 2.1963x; 1.0666x over previous
#include <cuda_runtime.h>
#include <cuda_fp16.h>
#include <cstdint>
#include <math.h>

// ---------------- problem constants (fixed by reference) ----------------
#define NG   100
#define NPG  500
#define EPG  4000
#define NN   (NG*NPG)      // 50000 nodes
#define NE   (NG*EPG)      // 400000 edges
#define HID  128
#define H4   512
#define PQW  1024          // P (512) || Q (512)
#define KSEL 2000          // ceil(0.5 * 4000)
#define MT_TOT 3125        // NN/16 m16-tiles

// output layout (float32, concatenated in reference return order)
#define O_ATT 0
#define O_CW  (NE)
#define O_SW  (2*NE)
#define O_CM  (3*NE)
#define O_EI  (4*NE)           // [2,E]: new_row then new_col
#define O_NM  (6*NE)
#define O_CX  (6*NE + NN)

// ---------------- scratch (__device__ globals; no allocation) ----------------
// A fragments (fp16x2-packed): [mt 3125][ks16 8][lane 32] -> uint4 {a0,a1,a2,a3}
__device__ uint4         g_ehi[(size_t)MT_TOT * 8 * 32];
__device__ uint4         g_elo[(size_t)MT_TOT * 8 * 32];
// B fragments: [half 2][nt 64][ks16 8][lane 32] -> uint2 {b0,b1}
__device__ uint2         g_wthi[2 * 64 * 8 * 32];
__device__ uint2         g_wtlo[2 * 64 * 8 * 32];
__device__ float         g_PQ[(size_t)NN * PQW];    // ~205 MB
__device__ unsigned char g_cmask[NE];
__device__ int           g_nm[NN];
__device__ int           g_scan[NN];
__device__ int           g_newid[NN];
__device__ int           g_bsum[128];

// ---------------- helpers ----------------
__device__ __forceinline__ unsigned int h2u(__half2 h) { return *(unsigned int*)&h; }

__device__ __forceinline__ void split_f2(float2 v, unsigned int& hi, unsigned int& lo) {
    __half2 h = __float22half2_rn(v);
    float2 hf = __half22float2(h);
    __half2 l = __float22half2_rn(make_float2(v.x - hf.x, v.y - hf.y));
    hi = h2u(h); lo = h2u(l);
}

__device__ __forceinline__ unsigned int f2k(float f) {
    unsigned int u = __float_as_uint(f);
    return (u & 0x80000000u) ? ~u : (u | 0x80000000u);
}
__device__ __forceinline__ float k2f(unsigned int k) {
    unsigned int u = (k & 0x80000000u) ? (k & 0x7FFFFFFFu) : ~k;
    return __uint_as_float(u);
}

// ---------------- warp-level fp16 MMA m16n8k16 (baseline PTX) ----------------
__device__ __forceinline__ void mma_f16(float* d, uint4 a, uint2 b) {
    asm volatile(
        "mma.sync.aligned.m16n8k16.row.col.f32.f16.f16.f32 "
        "{%0,%1,%2,%3}, {%4,%5,%6,%7}, {%8,%9}, {%0,%1,%2,%3};"
        : "+f"(d[0]), "+f"(d[1]), "+f"(d[2]), "+f"(d[3])
        : "r"(a.x), "r"(a.y), "r"(a.z), "r"(a.w), "r"(b.x), "r"(b.y));
}

// ---------------- K1 (launch 1): fused split of emb and W1 into fp16 hi/lo fragments ----
// blocks 0..127: W tasks (8 warps each, 1024 tasks); blocks 128..3252: emb tasks (25000).
__global__ __launch_bounds__(256) void k_split_all(const float* __restrict__ emb,
                                                   const float* __restrict__ W1) {
    int wid  = threadIdx.x >> 5;
    int lane = threadIdx.x & 31;
    int g = lane >> 2, t = lane & 3;
    if (blockIdx.x < 128) {
        int task = blockIdx.x * 8 + wid;        // 0 .. 1023 exact
        int half = task >> 9;
        int nt   = (task >> 3) & 63;
        int ks   = task & 7;
        int n  = nt * 8 + g;
        int k0 = half * 128 + ks * 16 + 2 * t;
        float2 v0 = make_float2(W1[(size_t)k0 * H4 + n], W1[(size_t)(k0 + 1) * H4 + n]);
        float2 v1 = make_float2(W1[(size_t)(k0 + 8) * H4 + n], W1[(size_t)(k0 + 9) * H4 + n]);
        uint2 h, l;
        split_f2(v0, h.x, l.x);
        split_f2(v1, h.y, l.y);
        size_t idx = (size_t)task * 32 + lane;
        g_wthi[idx] = h;
        g_wtlo[idx] = l;
    } else {
        int task = (blockIdx.x - 128) * 8 + wid;  // 0 .. 25000-1 exact
        int mt = task >> 3;
        int ks = task & 7;
        int r0 = mt * 16 + g;
        int c0 = ks * 16 + 2 * t;
        float2 v00 = *(const float2*)(emb + (size_t)r0 * HID + c0);
        float2 v10 = *(const float2*)(emb + (size_t)(r0 + 8) * HID + c0);
        float2 v02 = *(const float2*)(emb + (size_t)r0 * HID + c0 + 8);
        float2 v12 = *(const float2*)(emb + (size_t)(r0 + 8) * HID + c0 + 8);
        uint4 h, l;
        split_f2(v00, h.x, l.x);
        split_f2(v10, h.y, l.y);
        split_f2(v02, h.z, l.z);
        split_f2(v12, h.w, l.w);
        size_t idx = (size_t)task * 32 + lane;
        g_ehi[idx] = h;
        g_elo[idx] = l;
    }
}

// ---------------- K2 (launch 2): zero node-mask ----------------
__global__ void k_zero_nm() {
    int n = blockIdx.x * blockDim.x + threadIdx.x;
    if (n < NN) g_nm[n] = 0;
}

// ---------------- K3 (launch 3): 3xFP16 GEMM via mma.sync m16n8k16 (R10 config) ----------------
// grid (16, 391): x = 64-wide n-tile of PQ, y = 128-row m-tile (8 m16-tiles).
// CTA 128m x 64n, 8 warps (warpM 2 x warpN 4), warp = 64m x 16n. smem 96KB -> 2 CTAs/SM.
#define SB_HI 0          // float offsets
#define SB_LO 4096       // B: 8nt*8ks*32 uint2 = 16KB each
#define SA_HI 8192       // A: 8mt*8ks*32 uint4 = 32KB each
#define SA_LO 16384
#define GEMM_DYN (24576*4)   // 98304 bytes

extern __shared__ float gsm[];

__global__ __launch_bounds__(256, 2) void k_gemm_mma(const float* __restrict__ b1) {
    int tid   = threadIdx.x;
    int wid   = tid >> 5;
    int lane  = tid & 31;
    int gquad = lane >> 2;
    int tg    = lane & 3;
    int nbase = blockIdx.x * 64;
    int mbase16 = blockIdx.y * 8;

    int warpM = wid & 1;                   // 2 x 64 rows
    int warpN = wid >> 1;                  // 4 x 16 cols

    int half = nbase >> 9;                 // 0 = P, 1 = Q
    int ntb  = (nbase & 511) >> 3;         // first n8-tile within half (8 per CTA)

    // ---- stage B (8 nt x 8 ks, hi+lo): contiguous copy ----
    {
        size_t src4 = ((size_t)(half * 64 + ntb) * 256) >> 1;   // float4 index into g_wthi
        const float4* sh = (const float4*)g_wthi + src4;
        const float4* sl = (const float4*)g_wtlo + src4;
        #pragma unroll
        for (int l = 0; l < 4; l++) {
            int t = tid + l * 256;                              // 0..1023 float4
            ((float4*)(gsm + SB_HI))[t] = sh[t];
            ((float4*)(gsm + SB_LO))[t] = sl[t];
        }
    }
    // ---- stage A (8 mt x 8 ks, hi+lo): contiguous copy with mt guard ----
    {
        const float4* sh = (const float4*)g_ehi + (size_t)mbase16 * 256;
        const float4* sl = (const float4*)g_elo + (size_t)mbase16 * 256;
        #pragma unroll
        for (int l = 0; l < 8; l++) {
            int t  = tid + l * 256;                             // 0..2047 float4
            int mt = t >> 8;
            float4 vh = make_float4(0.f, 0.f, 0.f, 0.f), vl = vh;
            if (mbase16 + mt < MT_TOT) { vh = sh[t]; vl = sl[t]; }
            ((float4*)(gsm + SA_HI))[t] = vh;
            ((float4*)(gsm + SA_LO))[t] = vl;
        }
    }
    __syncthreads();

    float acc[4][2][4];
    #pragma unroll
    for (int i = 0; i < 4; i++)
        #pragma unroll
        for (int j = 0; j < 2; j++)
            #pragma unroll
            for (int r = 0; r < 4; r++) acc[i][j][r] = 0.f;

    #pragma unroll
    for (int ks = 0; ks < 8; ks++) {
        uint4 ah[4], al[4];
        #pragma unroll
        for (int i = 0; i < 4; i++) {
            int idx = ((warpM * 4 + i) * 8 + ks) * 32 + lane;
            ah[i] = ((const uint4*)(gsm + SA_HI))[idx];
            al[i] = ((const uint4*)(gsm + SA_LO))[idx];
        }
        uint2 bh[2], bl[2];
        #pragma unroll
        for (int j = 0; j < 2; j++) {
            int idx = ((warpN * 2 + j) * 8 + ks) * 32 + lane;
            bh[j] = ((const uint2*)(gsm + SB_HI))[idx];
            bl[j] = ((const uint2*)(gsm + SB_LO))[idx];
        }
        // pass 1: ah * bh (8 independent MMAs)
        #pragma unroll
        for (int j = 0; j < 2; j++)
            #pragma unroll
            for (int i = 0; i < 4; i++) mma_f16(acc[i][j], ah[i], bh[j]);
        // pass 2: ah * bl
        #pragma unroll
        for (int j = 0; j < 2; j++)
            #pragma unroll
            for (int i = 0; i < 4; i++) mma_f16(acc[i][j], ah[i], bl[j]);
        // pass 3: al * bh
        #pragma unroll
        for (int j = 0; j < 2; j++)
            #pragma unroll
            for (int i = 0; i < 4; i++) mma_f16(acc[i][j], al[i], bh[j]);
    }

    // ---- epilogue: add b1 (P half), store float2 pairs ----
    int mbase = mbase16 * 16;
    #pragma unroll
    for (int j = 0; j < 2; j++) {
        int col = nbase + warpN * 16 + j * 8 + 2 * tg;   // even
        float2 bv = make_float2(0.f, 0.f);
        if (col < H4) bv = *(const float2*)(b1 + col);
        #pragma unroll
        for (int i = 0; i < 4; i++) {
            int row0 = mbase + warpM * 64 + i * 16 + gquad;
            float* d = acc[i][j];
            if (row0 < NN)
                *(float2*)(g_PQ + (size_t)row0 * PQW + col) =
                    make_float2(d[0] + bv.x, d[1] + bv.y);
            if (row0 + 8 < NN)
                *(float2*)(g_PQ + (size_t)(row0 + 8) * PQW + col) =
                    make_float2(d[2] + bv.x, d[3] + bv.y);
        }
    }
}

// ---------------- K4 (launch 4 -> ncu target): edge attention, one warp per edge ----------------
__global__ __launch_bounds__(256) void k_edge_att(const int* __restrict__ ei,
                                                  const float* __restrict__ W2,
                                                  const float* __restrict__ b2,
                                                  float* __restrict__ out) {
    __shared__ __align__(16) float sw2[H4];
    int tid = threadIdx.x;
    for (int i = tid; i < H4; i += blockDim.x) sw2[i] = W2[i];
    __syncthreads();

    int gw   = (blockIdx.x * blockDim.x + tid) >> 5;
    int lane = tid & 31;
    if (gw >= NE) return;
    int r = ei[gw];
    int c = ei[NE + gw];
    const float4* Pr = (const float4*)(g_PQ + (size_t)r * PQW);
    const float4* Qr = (const float4*)(g_PQ + (size_t)c * PQW + H4);
    const float4* W4 = (const float4*)sw2;

    float acc = 0.f;
    #pragma unroll
    for (int it = 0; it < 4; it++) {
        int j4 = it * 32 + lane;
        float4 p = Pr[j4];
        float4 q = Qr[j4];
        float4 ww = W4[j4];
        acc += ww.x * fmaxf(p.x + q.x, 0.f);
        acc += ww.y * fmaxf(p.y + q.y, 0.f);
        acc += ww.z * fmaxf(p.z + q.z, 0.f);
        acc += ww.w * fmaxf(p.w + q.w, 0.f);
    }
    #pragma unroll
    for (int off = 16; off > 0; off >>= 1)
        acc += __shfl_xor_sync(0xFFFFFFFFu, acc, off);
    if (lane == 0) out[O_ATT + gw] = acc + b2[0];
}

// ---------------- K5: per-graph top-k radix select (512 thr, shuffle scans) ----------------
__global__ __launch_bounds__(512) void k_select(const int* __restrict__ ei,
                                                float* __restrict__ out) {
    __shared__ unsigned int skey[EPG];     // 16KB
    __shared__ int hist[256];
    __shared__ int wtmp[16];
    __shared__ unsigned int s_prefix;
    __shared__ int s_kleft;

    int g    = blockIdx.x;
    int tid  = threadIdx.x;
    int lane = tid & 31;
    int wid  = tid >> 5;
    int base = g * EPG;

    for (int i = tid; i < EPG; i += 512) skey[i] = f2k(out[O_ATT + base + i]);
    __syncthreads();

    unsigned int prefix = 0u;
    int kleft = KSEL;
    #pragma unroll
    for (int pass = 3; pass >= 0; pass--) {
        int shift = pass * 8;
        if (tid < 256) hist[tid] = 0;
        __syncthreads();
        unsigned int maskHigh = (pass == 3) ? 0u : (0xFFFFFFFFu << (shift + 8));
        for (int i = tid; i < EPG; i += 512) {
            unsigned int k = skey[i];
            if ((k & maskHigh) == prefix)
                atomicAdd(&hist[(k >> shift) & 255], 1);
        }
        __syncthreads();
        int myh = 0, sfx = 0;
        if (tid < 256) {
            myh = hist[tid];
            sfx = myh;
            #pragma unroll
            for (int off = 1; off < 32; off <<= 1) {
                int t = __shfl_down_sync(0xFFFFFFFFu, sfx, off);
                if (lane + off < 32) sfx += t;
            }
            if (lane == 0) wtmp[wid] = sfx;
        }
        __syncthreads();
        if (tid < 32) {
            int v = (tid < 8) ? wtmp[tid] : 0;
            #pragma unroll
            for (int off = 1; off < 8; off <<= 1) {
                int t = __shfl_down_sync(0xFFFFFFFFu, v, off);
                if (tid + off < 8) v += t;
            }
            if (tid < 8) wtmp[8 + tid] = v;
        }
        __syncthreads();
        if (tid < 256) {
            int incl  = sfx + ((wid < 7) ? wtmp[8 + wid + 1] : 0);
            int above = incl - myh;
            if (above < kleft && incl >= kleft) {
                s_prefix = prefix | ((unsigned int)tid << shift);
                s_kleft  = kleft - above;
            }
        }
        __syncthreads();
        prefix = s_prefix;
        kleft  = s_kleft;
    }
    __syncthreads();
    unsigned int T = prefix;
    int need = kleft;

    // ordered prefix over equality flags; 512*8=4096 > EPG=4000 -> guard everything
    int start = tid * 8;
    int localEq = 0;
    #pragma unroll
    for (int i = 0; i < 8; i++) {
        int idx = start + i;
        if (idx < EPG) localEq += (skey[idx] == T);
    }
    int p = localEq;
    #pragma unroll
    for (int off = 1; off < 32; off <<= 1) {
        int t = __shfl_up_sync(0xFFFFFFFFu, p, off);
        if (lane >= off) p += t;
    }
    if (lane == 31) wtmp[wid] = p;
    __syncthreads();
    if (tid < 32) {
        int v = (tid < 16) ? wtmp[tid] : 0;
        #pragma unroll
        for (int off = 1; off < 16; off <<= 1) {
            int t = __shfl_up_sync(0xFFFFFFFFu, v, off);
            if (tid >= off) v += t;
        }
        if (tid < 16) wtmp[tid] = v;
    }
    __syncthreads();
    int run = (p - localEq) + ((wid > 0) ? wtmp[wid - 1] : 0);

    for (int i = start; i < start + 8 && i < EPG; i++) {
        unsigned int k = skey[i];
        bool causal;
        if (k > T)       causal = true;
        else if (k == T) { causal = (run < need); run++; }
        else             causal = false;
        float att = k2f(k);
        int e = base + i;
        out[O_CW + e] = causal ? att : 0.f;
        out[O_SW + e] = causal ? 0.f : att;
        out[O_CM + e] = causal ? 1.f : 0.f;
        g_cmask[e] = causal ? 1 : 0;
        if (causal) {
            g_nm[ei[e]]      = 1;
            g_nm[ei[NE + e]] = 1;
        }
    }
}

// ---------------- K6/K7: two-level scan of node mask ----------------
__global__ __launch_bounds__(512) void k_scan_a() {
    __shared__ int s[512];
    int tid = threadIdx.x;
    int n = blockIdx.x * 512 + tid;
    int x = (n < NN) ? g_nm[n] : 0;
    s[tid] = x;
    __syncthreads();
    for (int off = 1; off < 512; off <<= 1) {
        int v = (tid >= off) ? s[tid - off] : 0;
        __syncthreads();
        s[tid] += v;
        __syncthreads();
    }
    if (n < NN) g_scan[n] = s[tid];
    if (tid == 511) g_bsum[blockIdx.x] = s[511];
}

__global__ void k_scan_b(int nblk) {
    if (threadIdx.x == 0 && blockIdx.x == 0) {
        int running = 0;
        for (int b = 0; b < nblk; b++) {
            int t = g_bsum[b];
            g_bsum[b] = running;
            running += t;
        }
    }
}

// ---------------- K8: fused node finalize (new_id, node_mask) + causal_x copy ----------------
__global__ void k_nodes(const float* __restrict__ emb, float* __restrict__ out) {
    int i = blockIdx.x * blockDim.x + threadIdx.x;
    if (i >= NN * 32) return;
    int node = i >> 5;
    int nmv = g_nm[node];
    float4 v = make_float4(0.f, 0.f, 0.f, 0.f);
    if (nmv) v = ((const float4*)emb)[i];
    ((float4*)(out + O_CX))[i] = v;
    if ((i & 31) == 0) {
        out[O_NM + node] = nmv ? 1.f : 0.f;
        g_newid[node] = g_scan[node] + g_bsum[node >> 9] - 1;
    }
}

// ---------------- K9: relabeled edge index ----------------
__global__ void k_edge_out(const int* __restrict__ ei, float* __restrict__ out) {
    int e = blockIdx.x * blockDim.x + threadIdx.x;
    if (e >= NE) return;
    bool c = g_cmask[e] != 0;
    int r = ei[e], cc = ei[NE + e];
    out[O_EI + e]      = c ? (float)g_newid[r]  : -1.f;
    out[O_EI + NE + e] = c ? (float)g_newid[cc] : -1.f;
}

// ---------------- launch ----------------
extern "C" void kernel_launch(void* const* d_in, const int* in_sizes, int n_in,
                              void* d_out, int out_size) {
    const float* emb = (const float*)d_in[0];
    const int*   ei  = (const int*)d_in[1];
    // d_in[2] = node_batch (implied by layout: graph = e / EPG)
    const float* W1  = (const float*)d_in[3];
    const float* b1  = (const float*)d_in[4];
    const float* W2  = (const float*)d_in[5];
    const float* b2  = (const float*)d_in[6];
    float* out = (float*)d_out;

    k_split_all<<<128 + MT_TOT, 256>>>(emb, W1);   // launch 1
    k_zero_nm<<<(NN + 255) / 256, 256>>>();        // launch 2

    cudaFuncSetAttribute(k_gemm_mma, cudaFuncAttributeMaxDynamicSharedMemorySize, GEMM_DYN);
    dim3 ggrid(PQW / 64, (NN + 127) / 128);        // (16, 391)
    k_gemm_mma<<<ggrid, 256, GEMM_DYN>>>(b1);      // launch 3

    k_edge_att<<<(NE * 32 + 255) / 256, 256>>>(ei, W2, b2, out);   // launch 4 (profiled)

    k_select<<<NG, 512>>>(ei, out);

    int nblk = (NN + 511) / 512;            // 98
    k_scan_a<<<nblk, 512>>>();
    k_scan_b<<<1, 32>>>(nblk);

    k_nodes<<<(NN * 32 + 255) / 256, 256>>>(emb, out);
    k_edge_out<<<(NE + 255) / 256, 256>>>(ei, out);
}

// round 16
// speedup vs baseline: 2.2070x; 1.0049x over previous
#include <cuda_runtime.h>
#include <cuda_fp16.h>
#include <cstdint>
#include <math.h>

// ---------------- problem constants (fixed by reference) ----------------
#define NG   100
#define NPG  500
#define EPG  4000
#define NN   (NG*NPG)      // 50000 nodes
#define NE   (NG*EPG)      // 400000 edges
#define HID  128
#define H4   512
#define PQW  1024          // P (512) || Q (512)
#define KSEL 2000          // ceil(0.5 * 4000)
#define MT_TOT 3125        // NN/16 m16-tiles

// output layout (float32, concatenated in reference return order)
#define O_ATT 0
#define O_CW  (NE)
#define O_SW  (2*NE)
#define O_CM  (3*NE)
#define O_EI  (4*NE)           // [2,E]: new_row then new_col
#define O_NM  (6*NE)
#define O_CX  (6*NE + NN)

// ---------------- scratch (__device__ globals; no allocation) ----------------
// A fragments (fp16x2-packed): [mt 3125][ks16 8][lane 32] -> uint4 {a0,a1,a2,a3}
__device__ uint4         g_ehi[(size_t)MT_TOT * 8 * 32];
__device__ uint4         g_elo[(size_t)MT_TOT * 8 * 32];
// B fragments: [half 2][nt 64][ks16 8][lane 32] -> uint2 {b0,b1}
__device__ uint2         g_wthi[2 * 64 * 8 * 32];
__device__ uint2         g_wtlo[2 * 64 * 8 * 32];
__device__ float         g_PQ[(size_t)NN * PQW];    // ~205 MB
__device__ unsigned char g_cmask[NE];
__device__ int           g_nm[NN];
__device__ int           g_scan[NN];
__device__ int           g_newid[NN];
__device__ int           g_bsum[128];

typedef unsigned long long u64;

// ---------------- packed f32x2 helpers (add/fma only — max.f32x2 does NOT exist) ----------------
__device__ __forceinline__ u64 f2x2_add(u64 a, u64 b) {
    u64 r; asm("add.rn.f32x2 %0, %1, %2;" : "=l"(r) : "l"(a), "l"(b)); return r;
}
__device__ __forceinline__ void f2x2_fma(u64& d, u64 a, u64 b) {
    asm("fma.rn.f32x2 %0, %1, %2, %0;" : "+l"(d) : "l"(a), "l"(b));
}
__device__ __forceinline__ u64 pack2(float lo, float hi) {
    u64 r; asm("mov.b64 %0, {%1,%2};" : "=l"(r) : "f"(lo), "f"(hi)); return r;
}
__device__ __forceinline__ void unpack2(u64 v, float& lo, float& hi) {
    asm("mov.b64 {%0,%1}, %2;" : "=f"(lo), "=f"(hi) : "l"(v));
}
// relu on a packed pair: unpack (reg-pair alias, free), 2x scalar FMNMX, repack (free)
__device__ __forceinline__ u64 f2x2_relu(u64 a) {
    float lo, hi;
    unpack2(a, lo, hi);
    return pack2(fmaxf(lo, 0.f), fmaxf(hi, 0.f));
}

// ---------------- helpers ----------------
__device__ __forceinline__ unsigned int h2u(__half2 h) { return *(unsigned int*)&h; }

__device__ __forceinline__ void split_f2(float2 v, unsigned int& hi, unsigned int& lo) {
    __half2 h = __float22half2_rn(v);
    float2 hf = __half22float2(h);
    __half2 l = __float22half2_rn(make_float2(v.x - hf.x, v.y - hf.y));
    hi = h2u(h); lo = h2u(l);
}

__device__ __forceinline__ unsigned int f2k(float f) {
    unsigned int u = __float_as_uint(f);
    return (u & 0x80000000u) ? ~u : (u | 0x80000000u);
}
__device__ __forceinline__ float k2f(unsigned int k) {
    unsigned int u = (k & 0x80000000u) ? (k & 0x7FFFFFFFu) : ~k;
    return __uint_as_float(u);
}

// ---------------- warp-level fp16 MMA m16n8k16 (baseline PTX) ----------------
__device__ __forceinline__ void mma_f16(float* d, uint4 a, uint2 b) {
    asm volatile(
        "mma.sync.aligned.m16n8k16.row.col.f32.f16.f16.f32 "
        "{%0,%1,%2,%3}, {%4,%5,%6,%7}, {%8,%9}, {%0,%1,%2,%3};"
        : "+f"(d[0]), "+f"(d[1]), "+f"(d[2]), "+f"(d[3])
        : "r"(a.x), "r"(a.y), "r"(a.z), "r"(a.w), "r"(b.x), "r"(b.y));
}

// ---------------- K1 (launch 1): fused split of emb and W1 into fp16 hi/lo fragments ----
// blocks 0..127: W tasks (8 warps each, 1024 tasks); blocks 128..3252: emb tasks (25000).
__global__ __launch_bounds__(256) void k_split_all(const float* __restrict__ emb,
                                                   const float* __restrict__ W1) {
    int wid  = threadIdx.x >> 5;
    int lane = threadIdx.x & 31;
    int g = lane >> 2, t = lane & 3;
    if (blockIdx.x < 128) {
        int task = blockIdx.x * 8 + wid;        // 0 .. 1023 exact
        int half = task >> 9;
        int nt   = (task >> 3) & 63;
        int ks   = task & 7;
        int n  = nt * 8 + g;
        int k0 = half * 128 + ks * 16 + 2 * t;
        float2 v0 = make_float2(W1[(size_t)k0 * H4 + n], W1[(size_t)(k0 + 1) * H4 + n]);
        float2 v1 = make_float2(W1[(size_t)(k0 + 8) * H4 + n], W1[(size_t)(k0 + 9) * H4 + n]);
        uint2 h, l;
        split_f2(v0, h.x, l.x);
        split_f2(v1, h.y, l.y);
        size_t idx = (size_t)task * 32 + lane;
        g_wthi[idx] = h;
        g_wtlo[idx] = l;
    } else {
        int task = (blockIdx.x - 128) * 8 + wid;  // 0 .. 25000-1 exact
        int mt = task >> 3;
        int ks = task & 7;
        int r0 = mt * 16 + g;
        int c0 = ks * 16 + 2 * t;
        float2 v00 = *(const float2*)(emb + (size_t)r0 * HID + c0);
        float2 v10 = *(const float2*)(emb + (size_t)(r0 + 8) * HID + c0);
        float2 v02 = *(const float2*)(emb + (size_t)r0 * HID + c0 + 8);
        float2 v12 = *(const float2*)(emb + (size_t)(r0 + 8) * HID + c0 + 8);
        uint4 h, l;
        split_f2(v00, h.x, l.x);
        split_f2(v10, h.y, l.y);
        split_f2(v02, h.z, l.z);
        split_f2(v12, h.w, l.w);
        size_t idx = (size_t)task * 32 + lane;
        g_ehi[idx] = h;
        g_elo[idx] = l;
    }
}

// ---------------- K2 (launch 2): zero node-mask ----------------
__global__ void k_zero_nm() {
    int n = blockIdx.x * blockDim.x + threadIdx.x;
    if (n < NN) g_nm[n] = 0;
}

// ---------------- K3 (launch 3): 3xFP16 GEMM via mma.sync m16n8k16 (R10 config) ----------------
// grid (16, 391): x = 64-wide n-tile of PQ, y = 128-row m-tile (8 m16-tiles).
// CTA 128m x 64n, 8 warps (warpM 2 x warpN 4), warp = 64m x 16n. smem 96KB -> 2 CTAs/SM.
#define SB_HI 0          // float offsets
#define SB_LO 4096       // B: 8nt*8ks*32 uint2 = 16KB each
#define SA_HI 8192       // A: 8mt*8ks*32 uint4 = 32KB each
#define SA_LO 16384
#define GEMM_DYN (24576*4)   // 98304 bytes

extern __shared__ float gsm[];

__global__ __launch_bounds__(256, 2) void k_gemm_mma(const float* __restrict__ b1) {
    int tid   = threadIdx.x;
    int wid   = tid >> 5;
    int lane  = tid & 31;
    int gquad = lane >> 2;
    int tg    = lane & 3;
    int nbase = blockIdx.x * 64;
    int mbase16 = blockIdx.y * 8;

    int warpM = wid & 1;                   // 2 x 64 rows
    int warpN = wid >> 1;                  // 4 x 16 cols

    int half = nbase >> 9;                 // 0 = P, 1 = Q
    int ntb  = (nbase & 511) >> 3;         // first n8-tile within half (8 per CTA)

    // ---- stage B (8 nt x 8 ks, hi+lo): contiguous copy ----
    {
        size_t src4 = ((size_t)(half * 64 + ntb) * 256) >> 1;   // float4 index into g_wthi
        const float4* sh = (const float4*)g_wthi + src4;
        const float4* sl = (const float4*)g_wtlo + src4;
        #pragma unroll
        for (int l = 0; l < 4; l++) {
            int t = tid + l * 256;                              // 0..1023 float4
            ((float4*)(gsm + SB_HI))[t] = sh[t];
            ((float4*)(gsm + SB_LO))[t] = sl[t];
        }
    }
    // ---- stage A (8 mt x 8 ks, hi+lo): contiguous copy with mt guard ----
    {
        const float4* sh = (const float4*)g_ehi + (size_t)mbase16 * 256;
        const float4* sl = (const float4*)g_elo + (size_t)mbase16 * 256;
        #pragma unroll
        for (int l = 0; l < 8; l++) {
            int t  = tid + l * 256;                             // 0..2047 float4
            int mt = t >> 8;
            float4 vh = make_float4(0.f, 0.f, 0.f, 0.f), vl = vh;
            if (mbase16 + mt < MT_TOT) { vh = sh[t]; vl = sl[t]; }
            ((float4*)(gsm + SA_HI))[t] = vh;
            ((float4*)(gsm + SA_LO))[t] = vl;
        }
    }
    __syncthreads();

    float acc[4][2][4];
    #pragma unroll
    for (int i = 0; i < 4; i++)
        #pragma unroll
        for (int j = 0; j < 2; j++)
            #pragma unroll
            for (int r = 0; r < 4; r++) acc[i][j][r] = 0.f;

    #pragma unroll
    for (int ks = 0; ks < 8; ks++) {
        uint4 ah[4], al[4];
        #pragma unroll
        for (int i = 0; i < 4; i++) {
            int idx = ((warpM * 4 + i) * 8 + ks) * 32 + lane;
            ah[i] = ((const uint4*)(gsm + SA_HI))[idx];
            al[i] = ((const uint4*)(gsm + SA_LO))[idx];
        }
        uint2 bh[2], bl[2];
        #pragma unroll
        for (int j = 0; j < 2; j++) {
            int idx = ((warpN * 2 + j) * 8 + ks) * 32 + lane;
            bh[j] = ((const uint2*)(gsm + SB_HI))[idx];
            bl[j] = ((const uint2*)(gsm + SB_LO))[idx];
        }
        // pass 1: ah * bh (8 independent MMAs)
        #pragma unroll
        for (int j = 0; j < 2; j++)
            #pragma unroll
            for (int i = 0; i < 4; i++) mma_f16(acc[i][j], ah[i], bh[j]);
        // pass 2: ah * bl
        #pragma unroll
        for (int j = 0; j < 2; j++)
            #pragma unroll
            for (int i = 0; i < 4; i++) mma_f16(acc[i][j], ah[i], bl[j]);
        // pass 3: al * bh
        #pragma unroll
        for (int j = 0; j < 2; j++)
            #pragma unroll
            for (int i = 0; i < 4; i++) mma_f16(acc[i][j], al[i], bh[j]);
    }

    // ---- epilogue: add b1 (P half), store float2 pairs ----
    int mbase = mbase16 * 16;
    #pragma unroll
    for (int j = 0; j < 2; j++) {
        int col = nbase + warpN * 16 + j * 8 + 2 * tg;   // even
        float2 bv = make_float2(0.f, 0.f);
        if (col < H4) bv = *(const float2*)(b1 + col);
        #pragma unroll
        for (int i = 0; i < 4; i++) {
            int row0 = mbase + warpM * 64 + i * 16 + gquad;
            float* d = acc[i][j];
            if (row0 < NN)
                *(float2*)(g_PQ + (size_t)row0 * PQW + col) =
                    make_float2(d[0] + bv.x, d[1] + bv.y);
            if (row0 + 8 < NN)
                *(float2*)(g_PQ + (size_t)(row0 + 8) * PQW + col) =
                    make_float2(d[2] + bv.x, d[3] + bv.y);
        }
    }
}

// ---------------- K4 (launch 4 -> ncu target): edge attention, packed add/fma f32x2 ----------------
__global__ __launch_bounds__(256) void k_edge_att(const int* __restrict__ ei,
                                                  const float* __restrict__ W2,
                                                  const float* __restrict__ b2,
                                                  float* __restrict__ out) {
    __shared__ __align__(16) float sw2[H4];
    int tid = threadIdx.x;
    for (int i = tid; i < H4; i += blockDim.x) sw2[i] = W2[i];
    __syncthreads();

    int gw   = (blockIdx.x * blockDim.x + tid) >> 5;
    int lane = tid & 31;
    if (gw >= NE) return;
    int r = ei[gw];
    int c = ei[NE + gw];
    const float4* Pr = (const float4*)(g_PQ + (size_t)r * PQW) + lane;
    const float4* Qr = (const float4*)(g_PQ + (size_t)c * PQW + H4) + lane;
    const float4* W4 = (const float4*)sw2 + lane;

    u64 acc2a = 0ull, acc2b = 0ull;
    #pragma unroll
    for (int it = 0; it < 4; it++) {
        float4 p = Pr[it * 32];
        float4 q = Qr[it * 32];
        float4 w = W4[it * 32];
        const u64* p2 = (const u64*)&p;
        const u64* q2 = (const u64*)&q;
        const u64* w2 = (const u64*)&w;
        u64 s0 = f2x2_relu(f2x2_add(p2[0], q2[0]));
        u64 s1 = f2x2_relu(f2x2_add(p2[1], q2[1]));
        f2x2_fma(acc2a, s0, w2[0]);
        f2x2_fma(acc2b, s1, w2[1]);
    }
    float a0, a1, b0v, b1v;
    unpack2(acc2a, a0, a1);
    unpack2(acc2b, b0v, b1v);
    float acc = (a0 + a1) + (b0v + b1v);
    #pragma unroll
    for (int off = 16; off > 0; off >>= 1)
        acc += __shfl_xor_sync(0xFFFFFFFFu, acc, off);
    if (lane == 0) out[O_ATT + gw] = acc + b2[0];
}

// ---------------- K5: per-graph top-k radix select (512 thr, shuffle scans) ----------------
__global__ __launch_bounds__(512) void k_select(const int* __restrict__ ei,
                                                float* __restrict__ out) {
    __shared__ unsigned int skey[EPG];     // 16KB
    __shared__ int hist[256];
    __shared__ int wtmp[16];
    __shared__ unsigned int s_prefix;
    __shared__ int s_kleft;

    int g    = blockIdx.x;
    int tid  = threadIdx.x;
    int lane = tid & 31;
    int wid  = tid >> 5;
    int base = g * EPG;

    for (int i = tid; i < EPG; i += 512) skey[i] = f2k(out[O_ATT + base + i]);
    __syncthreads();

    unsigned int prefix = 0u;
    int kleft = KSEL;
    #pragma unroll
    for (int pass = 3; pass >= 0; pass--) {
        int shift = pass * 8;
        if (tid < 256) hist[tid] = 0;
        __syncthreads();
        unsigned int maskHigh = (pass == 3) ? 0u : (0xFFFFFFFFu << (shift + 8));
        for (int i = tid; i < EPG; i += 512) {
            unsigned int k = skey[i];
            if ((k & maskHigh) == prefix)
                atomicAdd(&hist[(k >> shift) & 255], 1);
        }
        __syncthreads();
        int myh = 0, sfx = 0;
        if (tid < 256) {
            myh = hist[tid];
            sfx = myh;
            #pragma unroll
            for (int off = 1; off < 32; off <<= 1) {
                int t = __shfl_down_sync(0xFFFFFFFFu, sfx, off);
                if (lane + off < 32) sfx += t;
            }
            if (lane == 0) wtmp[wid] = sfx;
        }
        __syncthreads();
        if (tid < 32) {
            int v = (tid < 8) ? wtmp[tid] : 0;
            #pragma unroll
            for (int off = 1; off < 8; off <<= 1) {
                int t = __shfl_down_sync(0xFFFFFFFFu, v, off);
                if (tid + off < 8) v += t;
            }
            if (tid < 8) wtmp[8 + tid] = v;
        }
        __syncthreads();
        if (tid < 256) {
            int incl  = sfx + ((wid < 7) ? wtmp[8 + wid + 1] : 0);
            int above = incl - myh;
            if (above < kleft && incl >= kleft) {
                s_prefix = prefix | ((unsigned int)tid << shift);
                s_kleft  = kleft - above;
            }
        }
        __syncthreads();
        prefix = s_prefix;
        kleft  = s_kleft;
    }
    __syncthreads();
    unsigned int T = prefix;
    int need = kleft;

    // ordered prefix over equality flags; 512*8=4096 > EPG=4000 -> guard everything
    int start = tid * 8;
    int localEq = 0;
    #pragma unroll
    for (int i = 0; i < 8; i++) {
        int idx = start + i;
        if (idx < EPG) localEq += (skey[idx] == T);
    }
    int p = localEq;
    #pragma unroll
    for (int off = 1; off < 32; off <<= 1) {
        int t = __shfl_up_sync(0xFFFFFFFFu, p, off);
        if (lane >= off) p += t;
    }
    if (lane == 31) wtmp[wid] = p;
    __syncthreads();
    if (tid < 32) {
        int v = (tid < 16) ? wtmp[tid] : 0;
        #pragma unroll
        for (int off = 1; off < 16; off <<= 1) {
            int t = __shfl_up_sync(0xFFFFFFFFu, v, off);
            if (tid >= off) v += t;
        }
        if (tid < 16) wtmp[tid] = v;
    }
    __syncthreads();
    int run = (p - localEq) + ((wid > 0) ? wtmp[wid - 1] : 0);

    for (int i = start; i < start + 8 && i < EPG; i++) {
        unsigned int k = skey[i];
        bool causal;
        if (k > T)       causal = true;
        else if (k == T) { causal = (run < need); run++; }
        else             causal = false;
        float att = k2f(k);
        int e = base + i;
        out[O_CW + e] = causal ? att : 0.f;
        out[O_SW + e] = causal ? 0.f : att;
        out[O_CM + e] = causal ? 1.f : 0.f;
        g_cmask[e] = causal ? 1 : 0;
        if (causal) {
            g_nm[ei[e]]      = 1;
            g_nm[ei[NE + e]] = 1;
        }
    }
}

// ---------------- K6/K7: two-level scan of node mask ----------------
__global__ __launch_bounds__(512) void k_scan_a() {
    __shared__ int s[512];
    int tid = threadIdx.x;
    int n = blockIdx.x * 512 + tid;
    int x = (n < NN) ? g_nm[n] : 0;
    s[tid] = x;
    __syncthreads();
    for (int off = 1; off < 512; off <<= 1) {
        int v = (tid >= off) ? s[tid - off] : 0;
        __syncthreads();
        s[tid] += v;
        __syncthreads();
    }
    if (n < NN) g_scan[n] = s[tid];
    if (tid == 511) g_bsum[blockIdx.x] = s[511];
}

__global__ void k_scan_b(int nblk) {
    if (threadIdx.x == 0 && blockIdx.x == 0) {
        int running = 0;
        for (int b = 0; b < nblk; b++) {
            int t = g_bsum[b];
            g_bsum[b] = running;
            running += t;
        }
    }
}

// ---------------- K8: fused node finalize (new_id, node_mask) + causal_x copy ----------------
__global__ void k_nodes(const float* __restrict__ emb, float* __restrict__ out) {
    int i = blockIdx.x * blockDim.x + threadIdx.x;
    if (i >= NN * 32) return;
    int node = i >> 5;
    int nmv = g_nm[node];
    float4 v = make_float4(0.f, 0.f, 0.f, 0.f);
    if (nmv) v = ((const float4*)emb)[i];
    ((float4*)(out + O_CX))[i] = v;
    if ((i & 31) == 0) {
        out[O_NM + node] = nmv ? 1.f : 0.f;
        g_newid[node] = g_scan[node] + g_bsum[node >> 9] - 1;
    }
}

// ---------------- K9: relabeled edge index ----------------
__global__ void k_edge_out(const int* __restrict__ ei, float* __restrict__ out) {
    int e = blockIdx.x * blockDim.x + threadIdx.x;
    if (e >= NE) return;
    bool c = g_cmask[e] != 0;
    int r = ei[e], cc = ei[NE + e];
    out[O_EI + e]      = c ? (float)g_newid[r]  : -1.f;
    out[O_EI + NE + e] = c ? (float)g_newid[cc] : -1.f;
}

// ---------------- launch ----------------
extern "C" void kernel_launch(void* const* d_in, const int* in_sizes, int n_in,
                              void* d_out, int out_size) {
    const float* emb = (const float*)d_in[0];
    const int*   ei  = (const int*)d_in[1];
    // d_in[2] = node_batch (implied by layout: graph = e / EPG)
    const float* W1  = (const float*)d_in[3];
    const float* b1  = (const float*)d_in[4];
    const float* W2  = (const float*)d_in[5];
    const float* b2  = (const float*)d_in[6];
    float* out = (float*)d_out;

    k_split_all<<<128 + MT_TOT, 256>>>(emb, W1);   // launch 1
    k_zero_nm<<<(NN + 255) / 256, 256>>>();        // launch 2

    cudaFuncSetAttribute(k_gemm_mma, cudaFuncAttributeMaxDynamicSharedMemorySize, GEMM_DYN);
    dim3 ggrid(PQW / 64, (NN + 127) / 128);        // (16, 391)
    k_gemm_mma<<<ggrid, 256, GEMM_DYN>>>(b1);      // launch 3

    k_edge_att<<<(NE * 32 + 255) / 256, 256>>>(ei, W2, b2, out);   // launch 4 (profiled)

    k_select<<<NG, 512>>>(ei, out);

    int nblk = (NN + 511) / 512;            // 98
    k_scan_a<<<nblk, 512>>>();
    k_scan_b<<<1, 32>>>(nblk);

    k_nodes<<<(NN * 32 + 255) / 256, 256>>>(emb, out);
    k_edge_out<<<(NE + 255) / 256, 256>>>(ei, out);
}